// round 8
// baseline (speedup 1.0000x reference)
#include <cuda_runtime.h>
#include <math.h>

#define NN   100000
#define EE   640000
#define HH   128
#define EMBD 96
#define SELD 32
#define PDIM 64
#define NPOS 513        // MAXPOS+1
#define NT   3
#define GITERS 6
#define WTS  388        // padded row pitch for transposed GRU weights in smem

#define EPW  16         // edges per warp (edge kernel)
#define EWPB 8          // warps per block (edge kernel)
#define EPB  (EPW*EWPB) // 128 edges per block; type segment bases aligned to this
#define PADE (EE + NT*EPB)   // 640384 sorted+padded edge slots

#define GNW 4           // warps per block (GRU kernels)
#define GNT 8           // nodes per warp tile (GRU kernels)
#define ONW 8           // warps per block (output kernel)
#define ONT 4           // nodes per warp tile (output kernel)

// ---------------- device scratch (no allocations allowed) ----------------
__device__ float d_h0 [NN * HH];
__device__ float d_hA [NN * HH];
__device__ float d_hB [NN * HH];
__device__ float d_agg[NN * HH];
__device__ float d_gi [NN * 3 * HH];
__device__ float d_gtab[NPOS * HH];      // gate table: 513 x 128 (262 KB, L2-resident)
__device__ float d_cnt[NN];
__device__ float d_inv[NN];
__device__ int   d_es[PADE];             // sorted src
__device__ int   d_ed[PADE];             // sorted dst (-1 = padding)
__device__ int   d_ps[PADE];             // sorted edge position
__device__ int   d_tcnt[NT];
__device__ int   d_cur[NT];
__device__ int   d_base[NT + 1];

__device__ __forceinline__ float sigf(float x) { return 1.0f / (1.0f + __expf(-x)); }

// ---- packed f32x2 helpers ----
__device__ __forceinline__ void fma2(unsigned long long& d, unsigned long long a,
                                     unsigned long long b) {
    asm("fma.rn.f32x2 %0, %1, %2, %0;" : "+l"(d) : "l"(a), "l"(b));
}
__device__ __forceinline__ unsigned long long pk2(float v) {
    unsigned long long r;
    asm("mov.b64 %0, {%1, %1};" : "=l"(r) : "f"(v));
    return r;
}
__device__ __forceinline__ float2 up2(unsigned long long v) {
    float2 r;
    asm("mov.b64 {%0, %1}, %2;" : "=f"(r.x), "=f"(r.y) : "l"(v));
    return r;
}
__device__ __forceinline__ void red4(float* p, float a, float b, float c, float d) {
    asm volatile("red.global.add.v4.f32 [%0], {%1, %2, %3, %4};"
                 :: "l"(p), "f"(a), "f"(b), "f"(c), "f"(d) : "memory");
}

// ---------------- setup kernels ----------------
__global__ void k_init_pad() {
    int i = blockIdx.x * blockDim.x + threadIdx.x;
    if (i < PADE) { d_ed[i] = -1; d_es[i] = 0; d_ps[i] = 0; }
    if (i < NT) { d_tcnt[i] = 0; d_cur[i] = 0; }
}
__global__ void k_hist(const int* __restrict__ et) {
    __shared__ int sc[NT];
    if (threadIdx.x < NT) sc[threadIdx.x] = 0;
    __syncthreads();
    int e = blockIdx.x * blockDim.x + threadIdx.x;
    if (e < EE) atomicAdd(&sc[et[e]], 1);
    __syncthreads();
    if (threadIdx.x < NT) atomicAdd(&d_tcnt[threadIdx.x], sc[threadIdx.x]);
}
__global__ void k_off() {
    int b = 0;
    for (int t = 0; t < NT; t++) {
        d_base[t] = b;
        b += ((d_tcnt[t] + EPB - 1) / EPB) * EPB;
    }
    d_base[NT] = b;
}
// block-aggregated counting-sort scatter: 3 global atomics per block
__global__ void k_perm(const int* __restrict__ src, const int* __restrict__ dst,
                       const int* __restrict__ et, const int* __restrict__ epos) {
    __shared__ int s_cnt[NT], s_base[NT];
    if (threadIdx.x < NT) s_cnt[threadIdx.x] = 0;
    __syncthreads();
    int e = blockIdx.x * blockDim.x + threadIdx.x;
    int t = 0, lr = 0;
    if (e < EE) { t = et[e]; lr = atomicAdd(&s_cnt[t], 1); }
    __syncthreads();
    if (threadIdx.x < NT) s_base[threadIdx.x] = atomicAdd(&d_cur[threadIdx.x], s_cnt[threadIdx.x]);
    __syncthreads();
    if (e < EE) {
        int p = d_base[t] + s_base[t] + lr;
        d_es[p] = src[e];
        d_ed[p] = dst[e];
        d_ps[p] = epos[e];
    }
}
__global__ void k_zero_cnt() {
    int i = blockIdx.x * blockDim.x + threadIdx.x;
    if (i < NN) d_cnt[i] = 0.0f;
}
__global__ void k_h0(const int* __restrict__ xidx, const float* __restrict__ sel,
                     const float* __restrict__ emb) {
    int t = blockIdx.x * blockDim.x + threadIdx.x;
    if (t >= NN * 32) return;
    int n = t >> 5;
    int q = (t & 31) * 4;
    float4 v;
    if (q < EMBD) v = *(const float4*)&emb[(long long)xidx[n] * EMBD + q];
    else          v = *(const float4*)&sel[n * SELD + (q - EMBD)];
    *(float4*)&d_h0[n * HH + q] = v;
    *(float4*)&d_hA[n * HH + q] = v;
}
__global__ void k_deg(const int* __restrict__ dst) {
    int e = blockIdx.x * blockDim.x + threadIdx.x;
    if (e < EE) atomicAdd(&d_cnt[dst[e]], 1.0f);
}
__global__ void k_inv() {
    int i = blockIdx.x * blockDim.x + threadIdx.x;
    if (i < NN) d_inv[i] = 1.0f / fmaxf(d_cnt[i], 1.0f);
}
__global__ void k_zero_agg() {
    int i = blockIdx.x * blockDim.x + threadIdx.x;
    if (i < NN * HH / 4) ((float4*)d_agg)[i] = make_float4(0.f, 0.f, 0.f, 0.f);
}

// gate table: d_gtab[p,:] = 2*sigmoid(pe[p] @ Wg + bg), one block per position
__global__ __launch_bounds__(128) void k_gtab(const float* __restrict__ pe,
                                              const float* __restrict__ Wg,
                                              const float* __restrict__ bg) {
    __shared__ float ps[PDIM];
    int p = blockIdx.x;
    if (threadIdx.x < PDIM) ps[threadIdx.x] = pe[p * PDIM + threadIdx.x];
    __syncthreads();
    int j = threadIdx.x;
    float a = 0.0f;
    #pragma unroll 8
    for (int k = 0; k < PDIM; k++) a += ps[k] * Wg[k * HH + j];
    d_gtab[p * HH + j] = 2.0f * sigf(a + bg[j]);
}

// edge phase: 16 edges/warp (single type per block via sort), dup staging,
// broadcast LDS.64 X reads, FFMA2, vector red.global.add.v4 scatter.
__global__ __launch_bounds__(256) void k_edge(const float* __restrict__ Wt,
                                              const float* __restrict__ bt,
                                              int flip) {
    extern __shared__ float sm[];
    float* Ws = sm;                      // 128*128
    float* Xs = sm + HH * HH;            // 8 warps * 16 edges * 256 (dup of 128)
    const float* __restrict__ h = flip ? d_hB : d_hA;
    int start = blockIdx.x * EPB;
    int t = (start >= d_base[1]) + (start >= d_base[2]);
    const float4* wg = (const float4*)(Wt + t * HH * HH);
    for (int i = threadIdx.x; i < HH * HH / 4; i += 256) ((float4*)Ws)[i] = wg[i];
    int lane = threadIdx.x & 31, w = threadIdx.x >> 5;
    float4 bb = *(const float4*)&bt[t * HH + 4 * lane];
    __syncthreads();
    float* X = Xs + w * (EPW * 2 * HH);
    int e0 = start + w * EPW;
    #pragma unroll
    for (int i = 0; i < EPW; i++) {
        int s = d_es[e0 + i];
        int p = d_ps[e0 + i];
        float4 hv = *(const float4*)&h[s * HH + 4 * lane];
        float4 gv = *(const float4*)&d_gtab[p * HH + 4 * lane];
        float x0 = hv.x * gv.x, x1 = hv.y * gv.y, x2 = hv.z * gv.z, x3 = hv.w * gv.w;
        float* xr = X + i * 2 * HH + 8 * lane;
        *(float4*)(xr)     = make_float4(x0, x0, x1, x1);
        *(float4*)(xr + 4) = make_float4(x2, x2, x3, x3);
    }
    __syncwarp();
    unsigned long long acc[EPW][2];
    #pragma unroll
    for (int i = 0; i < EPW; i++) { acc[i][0] = 0ull; acc[i][1] = 0ull; }
    #pragma unroll 4
    for (int k = 0; k < HH; k++) {
        ulonglong2 wv = *(const ulonglong2*)&Ws[k * HH + 4 * lane];
        #pragma unroll
        for (int i = 0; i < EPW; i++) {
            unsigned long long xk = *(const unsigned long long*)&X[i * 2 * HH + 2 * k];
            fma2(acc[i][0], xk, wv.x);
            fma2(acc[i][1], xk, wv.y);
        }
    }
    #pragma unroll
    for (int i = 0; i < EPW; i++) {
        int d = d_ed[e0 + i];
        if (d >= 0) {
            float invd = d_inv[d];
            float2 p0 = up2(acc[i][0]), p1 = up2(acc[i][1]);
            red4(&d_agg[d * HH + 4 * lane],
                 (p0.x + bb.x) * invd, (p0.y + bb.y) * invd,
                 (p1.x + bb.z) * invd, (p1.y + bb.w) * invd);
        }
    }
}

// gi = agg @ W_ih^T + b_ih, 8 nodes/warp, weights transposed in smem, FFMA2
__global__ __launch_bounds__(128) void k_gi(const float* __restrict__ Wih,
                                            const float* __restrict__ bih) {
    extern __shared__ float sm[];
    float* wt = sm;                      // [128][WTS]
    float* Xs = wt + HH * WTS;           // 4 warps * 8 nodes * 128
    for (int i = threadIdx.x; i < 3 * HH * HH; i += 128) {
        int j = i >> 7, k = i & 127;
        wt[k * WTS + j] = Wih[i];
    }
    int lane = threadIdx.x & 31, w = threadIdx.x >> 5;
    float4 b0 = *(const float4*)&bih[4 * lane];
    float4 b1 = *(const float4*)&bih[128 + 4 * lane];
    float4 b2 = *(const float4*)&bih[256 + 4 * lane];
    __syncthreads();
    float* X = Xs + w * (GNT * HH);
    int gw = blockIdx.x * GNW + w;
    for (int n0 = gw * GNT; n0 < NN; n0 += 148 * GNW * GNT) {
        #pragma unroll
        for (int i = 0; i < GNT; i++)
            *(float4*)&X[i * HH + 4 * lane] = *(const float4*)&d_agg[(n0 + i) * HH + 4 * lane];
        __syncwarp();
        unsigned long long acc[GNT][6];
        #pragma unroll
        for (int i = 0; i < GNT; i++)
            #pragma unroll
            for (int q = 0; q < 6; q++) acc[i][q] = 0ull;
        #pragma unroll 2
        for (int k = 0; k < HH; k++) {
            const float* row = &wt[k * WTS];
            ulonglong2 w0 = *(const ulonglong2*)&row[      4 * lane];
            ulonglong2 w1 = *(const ulonglong2*)&row[128 + 4 * lane];
            ulonglong2 w2 = *(const ulonglong2*)&row[256 + 4 * lane];
            #pragma unroll
            for (int i = 0; i < GNT; i++) {
                unsigned long long xp = pk2(X[i * HH + k]);
                fma2(acc[i][0], xp, w0.x); fma2(acc[i][1], xp, w0.y);
                fma2(acc[i][2], xp, w1.x); fma2(acc[i][3], xp, w1.y);
                fma2(acc[i][4], xp, w2.x); fma2(acc[i][5], xp, w2.y);
            }
        }
        #pragma unroll
        for (int i = 0; i < GNT; i++) {
            float* gp = &d_gi[(n0 + i) * 3 * HH];
            float2 q0 = up2(acc[i][0]), q1 = up2(acc[i][1]), q2 = up2(acc[i][2]);
            float2 q3 = up2(acc[i][3]), q4 = up2(acc[i][4]), q5 = up2(acc[i][5]);
            *(float4*)&gp[      4 * lane] = make_float4(q0.x + b0.x, q0.y + b0.y, q1.x + b0.z, q1.y + b0.w);
            *(float4*)&gp[128 + 4 * lane] = make_float4(q2.x + b1.x, q2.y + b1.y, q3.x + b1.z, q3.y + b1.w);
            *(float4*)&gp[256 + 4 * lane] = make_float4(q4.x + b2.x, q4.y + b2.y, q5.x + b2.z, q5.y + b2.w);
        }
        __syncwarp();
    }
}

// gh = h @ W_hh^T + b_hh, fused GRU combine -> h_next. Same tiling as k_gi.
__global__ __launch_bounds__(128) void k_gh(const float* __restrict__ Whh,
                                            const float* __restrict__ bhh,
                                            int flip) {
    extern __shared__ float sm[];
    float* wt = sm;
    float* Xs = wt + HH * WTS;
    for (int i = threadIdx.x; i < 3 * HH * HH; i += 128) {
        int j = i >> 7, k = i & 127;
        wt[k * WTS + j] = Whh[i];
    }
    int lane = threadIdx.x & 31, w = threadIdx.x >> 5;
    float4 b0 = *(const float4*)&bhh[4 * lane];
    float4 b1 = *(const float4*)&bhh[128 + 4 * lane];
    float4 b2 = *(const float4*)&bhh[256 + 4 * lane];
    __syncthreads();
    const float* __restrict__ h = flip ? d_hB : d_hA;
    float* __restrict__ hn      = flip ? d_hA : d_hB;
    float* X = Xs + w * (GNT * HH);
    int gw = blockIdx.x * GNW + w;
    for (int n0 = gw * GNT; n0 < NN; n0 += 148 * GNW * GNT) {
        #pragma unroll
        for (int i = 0; i < GNT; i++)
            *(float4*)&X[i * HH + 4 * lane] = *(const float4*)&h[(n0 + i) * HH + 4 * lane];
        __syncwarp();
        unsigned long long acc[GNT][6];
        #pragma unroll
        for (int i = 0; i < GNT; i++)
            #pragma unroll
            for (int q = 0; q < 6; q++) acc[i][q] = 0ull;
        #pragma unroll 2
        for (int k = 0; k < HH; k++) {
            const float* row = &wt[k * WTS];
            ulonglong2 w0 = *(const ulonglong2*)&row[      4 * lane];
            ulonglong2 w1 = *(const ulonglong2*)&row[128 + 4 * lane];
            ulonglong2 w2 = *(const ulonglong2*)&row[256 + 4 * lane];
            #pragma unroll
            for (int i = 0; i < GNT; i++) {
                unsigned long long xp = pk2(X[i * HH + k]);
                fma2(acc[i][0], xp, w0.x); fma2(acc[i][1], xp, w0.y);
                fma2(acc[i][2], xp, w1.x); fma2(acc[i][3], xp, w1.y);
                fma2(acc[i][4], xp, w2.x); fma2(acc[i][5], xp, w2.y);
            }
        }
        #pragma unroll
        for (int i = 0; i < GNT; i++) {
            float2 q0 = up2(acc[i][0]), q1 = up2(acc[i][1]), q2 = up2(acc[i][2]);
            float2 q3 = up2(acc[i][3]), q4 = up2(acc[i][4]), q5 = up2(acc[i][5]);
            float hr0 = q0.x + b0.x, hr1 = q0.y + b0.y, hr2 = q1.x + b0.z, hr3 = q1.y + b0.w;
            float hz0 = q2.x + b1.x, hz1 = q2.y + b1.y, hz2 = q3.x + b1.z, hz3 = q3.y + b1.w;
            float hn0 = q4.x + b2.x, hn1 = q4.y + b2.y, hn2 = q5.x + b2.z, hn3 = q5.y + b2.w;
            const float* gp = &d_gi[(n0 + i) * 3 * HH];
            float4 g0 = *(const float4*)&gp[      4 * lane];
            float4 g1 = *(const float4*)&gp[128 + 4 * lane];
            float4 g2 = *(const float4*)&gp[256 + 4 * lane];
            float4 hh = *(const float4*)&h[(n0 + i) * HH + 4 * lane];
            float4 o;
            { float r = sigf(g0.x + hr0); float z = sigf(g1.x + hz0);
              float nv = tanhf(g2.x + r * hn0); o.x = (1.0f - z) * nv + z * hh.x; }
            { float r = sigf(g0.y + hr1); float z = sigf(g1.y + hz1);
              float nv = tanhf(g2.y + r * hn1); o.y = (1.0f - z) * nv + z * hh.y; }
            { float r = sigf(g0.z + hr2); float z = sigf(g1.z + hz2);
              float nv = tanhf(g2.z + r * hn2); o.z = (1.0f - z) * nv + z * hh.z; }
            { float r = sigf(g0.w + hr3); float z = sigf(g1.w + hz3);
              float nv = tanhf(g2.w + r * hn3); o.w = (1.0f - z) * nv + z * hh.w; }
            *(float4*)&hn[(n0 + i) * HH + 4 * lane] = o;
        }
        __syncwarp();
    }
}

// logits = relu([h, h0] @ W1 + b1) @ W2 + b2, 4 nodes/warp, broadcast X, FFMA2
__global__ __launch_bounds__(256) void k_out(const float* __restrict__ W1,
                                             const float* __restrict__ b1,
                                             const float* __restrict__ W2,
                                             const float* __restrict__ b2,
                                             float* __restrict__ out) {
    extern __shared__ float sm[];
    float* Ws = sm;                      // 256*128
    float* Xs = sm + 2 * HH * HH;        // 8 warps * 4 nodes * 512 (dup of 256)
    for (int i = threadIdx.x; i < 2 * HH * HH / 4; i += 256)
        ((float4*)Ws)[i] = ((const float4*)W1)[i];
    int lane = threadIdx.x & 31, w = threadIdx.x >> 5;
    float4 bb = *(const float4*)&b1[4 * lane];
    float4 w2v = *(const float4*)&W2[4 * lane];
    float b2v = b2[0];
    __syncthreads();
    float* X = Xs + w * (ONT * 2 * 2 * HH);
    int gw = blockIdx.x * ONW + w;
    for (int n0 = gw * ONT; n0 < NN; n0 += 148 * ONW * ONT) {
        #pragma unroll
        for (int i = 0; i < ONT; i++) {
            float4 a = *(const float4*)&d_hA[(n0 + i) * HH + 4 * lane];
            float4 c = *(const float4*)&d_h0[(n0 + i) * HH + 4 * lane];
            float* xr = X + i * 512;
            *(float4*)(xr + 8 * lane)           = make_float4(a.x, a.x, a.y, a.y);
            *(float4*)(xr + 8 * lane + 4)       = make_float4(a.z, a.z, a.w, a.w);
            *(float4*)(xr + 256 + 8 * lane)     = make_float4(c.x, c.x, c.y, c.y);
            *(float4*)(xr + 256 + 8 * lane + 4) = make_float4(c.z, c.z, c.w, c.w);
        }
        __syncwarp();
        unsigned long long acc[ONT][2];
        #pragma unroll
        for (int i = 0; i < ONT; i++) { acc[i][0] = 0ull; acc[i][1] = 0ull; }
        #pragma unroll 4
        for (int k = 0; k < 2 * HH; k++) {
            ulonglong2 wv = *(const ulonglong2*)&Ws[k * HH + 4 * lane];
            #pragma unroll
            for (int i = 0; i < ONT; i++) {
                unsigned long long xk = *(const unsigned long long*)&X[i * 512 + 2 * k];
                fma2(acc[i][0], xk, wv.x);
                fma2(acc[i][1], xk, wv.y);
            }
        }
        #pragma unroll
        for (int i = 0; i < ONT; i++) {
            float2 p0 = up2(acc[i][0]), p1 = up2(acc[i][1]);
            float r0 = fmaxf(p0.x + bb.x, 0.f), r1 = fmaxf(p0.y + bb.y, 0.f);
            float r2 = fmaxf(p1.x + bb.z, 0.f), r3 = fmaxf(p1.y + bb.w, 0.f);
            float p = r0 * w2v.x + r1 * w2v.y + r2 * w2v.z + r3 * w2v.w;
            #pragma unroll
            for (int o = 16; o > 0; o >>= 1) p += __shfl_xor_sync(0xFFFFFFFFu, p, o);
            if (lane == 0) out[n0 + i] = p + b2v;
        }
        __syncwarp();
    }
}

// ---------------- launch ----------------
extern "C" void kernel_launch(void* const* d_in, const int* in_sizes, int n_in,
                              void* d_out, int out_size) {
    (void)in_sizes; (void)n_in; (void)out_size;
    const int*   xidx = (const int*)  d_in[0];
    const float* sel  = (const float*)d_in[1];
    const int*   eidx = (const int*)  d_in[2];
    const int*   et   = (const int*)  d_in[3];
    const int*   epos = (const int*)  d_in[4];
    const float* emb  = (const float*)d_in[5];
    const float* pe   = (const float*)d_in[6];
    const float* Wg   = (const float*)d_in[7];
    const float* bg   = (const float*)d_in[8];
    const float* Wt   = (const float*)d_in[9];
    const float* bt   = (const float*)d_in[10];
    const float* Wih  = (const float*)d_in[11];
    const float* Whh  = (const float*)d_in[12];
    const float* bih  = (const float*)d_in[13];
    const float* bhh  = (const float*)d_in[14];
    const float* W1   = (const float*)d_in[15];
    const float* b1   = (const float*)d_in[16];
    const float* W2   = (const float*)d_in[17];
    const float* b2   = (const float*)d_in[18];
    float* out = (float*)d_out;
    const int* src = eidx;
    const int* dst = eidx + EE;

    const int SM_EDGE = (HH * HH + EWPB * EPW * 2 * HH) * 4;        // 196,608
    const int SM_GRU  = (HH * WTS + GNW * GNT * HH) * 4;            // 215,040
    const int SM_OUT  = (2 * HH * HH + ONW * ONT * 2 * 2 * HH) * 4; // 196,608

    cudaFuncSetAttribute(k_edge, cudaFuncAttributeMaxDynamicSharedMemorySize, SM_EDGE);
    cudaFuncSetAttribute(k_gi,   cudaFuncAttributeMaxDynamicSharedMemorySize, SM_GRU);
    cudaFuncSetAttribute(k_gh,   cudaFuncAttributeMaxDynamicSharedMemorySize, SM_GRU);
    cudaFuncSetAttribute(k_out,  cudaFuncAttributeMaxDynamicSharedMemorySize, SM_OUT);

    // setup: type sort + degrees + h0 + gate table (all once per replay)
    k_init_pad<<<(PADE + 255) / 256, 256>>>();
    k_hist<<<(EE + 255) / 256, 256>>>(et);
    k_off<<<1, 1>>>();
    k_perm<<<(EE + 255) / 256, 256>>>(src, dst, et, epos);
    k_zero_cnt<<<(NN + 255) / 256, 256>>>();
    k_h0<<<(NN * 32 + 255) / 256, 256>>>(xidx, sel, emb);
    k_deg<<<(EE + 255) / 256, 256>>>(dst);
    k_inv<<<(NN + 255) / 256, 256>>>();
    k_gtab<<<NPOS, 128>>>(pe, Wg, bg);

    for (int it = 0; it < GITERS; it++) {
        int flip = it & 1;
        k_zero_agg<<<(NN * HH / 4 + 255) / 256, 256>>>();
        k_edge<<<PADE / EPB, 256, SM_EDGE>>>(Wt, bt, flip);
        k_gi<<<148, 128, SM_GRU>>>(Wih, bih);
        k_gh<<<148, 128, SM_GRU>>>(Whh, bhh, flip);
    }
    k_out<<<148, 256, SM_OUT>>>(W1, b1, W2, b2, out);
}

// round 10
// speedup vs baseline: 1.2023x; 1.2023x over previous
#include <cuda_runtime.h>
#include <math.h>
#include <stdint.h>

#define NN   100000
#define EE   640000
#define HH   128
#define EMBD 96
#define SELD 32
#define PDIM 64
#define NPOS 513
#define NT   3
#define GITERS 6
#define WTS  388

#define EPB  128
#define PADE (EE + NT*EPB)

#define GNW 4
#define GNT 8
#define ONW 8
#define ONT 4

// k_edge smem layout (bytes)
#define OF_BIAS 0
#define OF_AHI  512
#define OF_ALO  35328
#define OF_BHI  70144
#define OF_BLO  104960
#define OF_C    139776
#define SM_EDGE_BYTES 207360
#define APITCH  272            // 136 bf16 per row
#define CPITCH  132            // floats
#define WIMGSZ  69632          // per-type [hi 34816][lo 34816]

// ---------------- device scratch ----------------
__device__ float d_h0 [NN * HH];
__device__ float d_hA [NN * HH];
__device__ float d_hB [NN * HH];
__device__ float d_agg[NN * HH];
__device__ float d_gi [NN * 3 * HH];
__device__ float d_gtab[NPOS * HH];
__device__ float d_cnt[NN];
__device__ float d_inv[NN];
__device__ int   d_es[PADE];
__device__ int   d_ed[PADE];
__device__ int   d_ps[PADE];
__device__ int   d_tcnt[NT];
__device__ int   d_cur[NT];
__device__ int   d_base[NT + 1];
__device__ unsigned char d_wimg[NT * WIMGSZ];   // pre-split, pitched W^T bf16 images

__device__ __forceinline__ float sigf(float x) { return 1.0f / (1.0f + __expf(-x)); }

// ---- packed helpers ----
__device__ __forceinline__ void fma2(unsigned long long& d, unsigned long long a,
                                     unsigned long long b) {
    asm("fma.rn.f32x2 %0, %1, %2, %0;" : "+l"(d) : "l"(a), "l"(b));
}
__device__ __forceinline__ unsigned long long pk2(float v) {
    unsigned long long r;
    asm("mov.b64 %0, {%1, %1};" : "=l"(r) : "f"(v));
    return r;
}
__device__ __forceinline__ float2 up2(unsigned long long v) {
    float2 r;
    asm("mov.b64 {%0, %1}, %2;" : "=f"(r.x), "=f"(r.y) : "l"(v));
    return r;
}
__device__ __forceinline__ void red4(float* p, float a, float b, float c, float d) {
    asm volatile("red.global.add.v4.f32 [%0], {%1, %2, %3, %4};"
                 :: "l"(p), "f"(a), "f"(b), "f"(c), "f"(d) : "memory");
}
// pack (x,y) -> bf16x2, x in low half
__device__ __forceinline__ unsigned pkbf(float x, float y) {
    unsigned r;
    asm("cvt.rn.bf16x2.f32 %0, %1, %2;" : "=r"(r) : "f"(y), "f"(x));
    return r;
}
__device__ __forceinline__ void split2(float x, float y, unsigned& hi, unsigned& lo) {
    hi = pkbf(x, y);
    float xh = __uint_as_float(hi << 16);
    float yh = __uint_as_float(hi & 0xffff0000u);
    lo = pkbf(x - xh, y - yh);
}
__device__ __forceinline__ void mma_bf16(float c[4], const unsigned a[4], const unsigned b[2]) {
    asm volatile("mma.sync.aligned.m16n8k16.row.col.f32.bf16.bf16.f32 "
                 "{%0,%1,%2,%3}, {%4,%5,%6,%7}, {%8,%9}, {%0,%1,%2,%3};"
                 : "+f"(c[0]), "+f"(c[1]), "+f"(c[2]), "+f"(c[3])
                 : "r"(a[0]), "r"(a[1]), "r"(a[2]), "r"(a[3]), "r"(b[0]), "r"(b[1]));
}

// ---------------- setup kernels ----------------
__global__ void k_init_pad() {
    int i = blockIdx.x * blockDim.x + threadIdx.x;
    if (i < PADE) { d_ed[i] = -1; d_es[i] = 0; d_ps[i] = 0; }
    if (i < NT) { d_tcnt[i] = 0; d_cur[i] = 0; }
}
__global__ void k_hist(const int* __restrict__ et) {
    __shared__ int sc[NT];
    if (threadIdx.x < NT) sc[threadIdx.x] = 0;
    __syncthreads();
    int e = blockIdx.x * blockDim.x + threadIdx.x;
    if (e < EE) atomicAdd(&sc[et[e]], 1);
    __syncthreads();
    if (threadIdx.x < NT) atomicAdd(&d_tcnt[threadIdx.x], sc[threadIdx.x]);
}
__global__ void k_off() {
    int b = 0;
    for (int t = 0; t < NT; t++) {
        d_base[t] = b;
        b += ((d_tcnt[t] + EPB - 1) / EPB) * EPB;
    }
    d_base[NT] = b;
}
__global__ void k_perm(const int* __restrict__ src, const int* __restrict__ dst,
                       const int* __restrict__ et, const int* __restrict__ epos) {
    __shared__ int s_cnt[NT], s_base[NT];
    if (threadIdx.x < NT) s_cnt[threadIdx.x] = 0;
    __syncthreads();
    int e = blockIdx.x * blockDim.x + threadIdx.x;
    int t = 0, lr = 0;
    if (e < EE) { t = et[e]; lr = atomicAdd(&s_cnt[t], 1); }
    __syncthreads();
    if (threadIdx.x < NT) s_base[threadIdx.x] = atomicAdd(&d_cur[threadIdx.x], s_cnt[threadIdx.x]);
    __syncthreads();
    if (e < EE) {
        int p = d_base[t] + s_base[t] + lr;
        d_es[p] = src[e]; d_ed[p] = dst[e]; d_ps[p] = epos[e];
    }
}
__global__ void k_zero_cnt() {
    int i = blockIdx.x * blockDim.x + threadIdx.x;
    if (i < NN) d_cnt[i] = 0.0f;
}
__global__ void k_h0(const int* __restrict__ xidx, const float* __restrict__ sel,
                     const float* __restrict__ emb) {
    int t = blockIdx.x * blockDim.x + threadIdx.x;
    if (t >= NN * 32) return;
    int n = t >> 5, q = (t & 31) * 4;
    float4 v;
    if (q < EMBD) v = *(const float4*)&emb[(long long)xidx[n] * EMBD + q];
    else          v = *(const float4*)&sel[n * SELD + (q - EMBD)];
    *(float4*)&d_h0[n * HH + q] = v;
    *(float4*)&d_hA[n * HH + q] = v;
}
__global__ void k_deg(const int* __restrict__ dst) {
    int e = blockIdx.x * blockDim.x + threadIdx.x;
    if (e < EE) atomicAdd(&d_cnt[dst[e]], 1.0f);
}
__global__ void k_inv() {
    int i = blockIdx.x * blockDim.x + threadIdx.x;
    if (i < NN) d_inv[i] = 1.0f / fmaxf(d_cnt[i], 1.0f);
}
__global__ void k_zero_agg() {
    int i = blockIdx.x * blockDim.x + threadIdx.x;
    if (i < NN * HH / 4) ((float4*)d_agg)[i] = make_float4(0.f, 0.f, 0.f, 0.f);
}
__global__ __launch_bounds__(128) void k_gtab(const float* __restrict__ pe,
                                              const float* __restrict__ Wg,
                                              const float* __restrict__ bg) {
    __shared__ float ps[PDIM];
    int p = blockIdx.x;
    if (threadIdx.x < PDIM) ps[threadIdx.x] = pe[p * PDIM + threadIdx.x];
    __syncthreads();
    int j = threadIdx.x;
    float a = 0.0f;
    #pragma unroll 8
    for (int k = 0; k < PDIM; k++) a += ps[k] * Wg[k * HH + j];
    d_gtab[p * HH + j] = 2.0f * sigf(a + bg[j]);
}
// W^T images: WT[n][k] = Wt[t][k][n], bf16 hi/lo, 272B row pitch (matches smem)
__global__ void k_wimg(const float* __restrict__ Wt) {
    int t = blockIdx.x;
    unsigned char* wh = d_wimg + t * WIMGSZ;
    unsigned char* wl = wh + 34816;
    for (int i = threadIdx.x; i < 128 * 64; i += blockDim.x) {
        int n = i >> 6, k = (i & 63) * 2;
        float v0 = Wt[t * HH * HH + k * HH + n];
        float v1 = Wt[t * HH * HH + (k + 1) * HH + n];
        unsigned hi, lo;
        split2(v0, v1, hi, lo);
        int o = n * APITCH + k * 2;
        *(unsigned*)(wh + o) = hi;
        *(unsigned*)(wl + o) = lo;
    }
}

// ---------------- edge phase: HMMA bf16x3 GEMM per 128-edge tile ----------------
__global__ __launch_bounds__(256) void k_edge(const float* __restrict__ bt, int flip) {
    extern __shared__ char smc[];
    int tid = threadIdx.x, wid = tid >> 5, lane = tid & 31;
    const float* __restrict__ h = flip ? d_hB : d_hA;
    int start = blockIdx.x * EPB;
    int t = (start >= d_base[1]) + (start >= d_base[2]);

    if (tid < 128) {
        *(float*)(smc + OF_BIAS + 4 * tid) = bt[t * HH + tid];
        // A staging: one edge row per thread, split hi/lo into pitched smem
        int r = tid;
        int s = d_es[start + r], pp = d_ps[start + r];
        const float4* hv = (const float4*)&h[s * HH];
        const float4* gv = (const float4*)&d_gtab[pp * HH];
        char* arh = smc + OF_AHI + r * APITCH;
        char* arl = smc + OF_ALO + r * APITCH;
        #pragma unroll 8
        for (int i = 0; i < 32; i++) {
            float4 a = hv[i], gg = gv[i];
            unsigned h0, l0, h1, l1;
            split2(a.x * gg.x, a.y * gg.y, h0, l0);
            split2(a.z * gg.z, a.w * gg.w, h1, l1);
            *(uint2*)(arh + i * 8) = make_uint2(h0, h1);
            *(uint2*)(arl + i * 8) = make_uint2(l0, l1);
        }
    } else {
        // B copy: verbatim pitched image [hi][lo]
        int idx = tid - 128;
        const uint4* sp = (const uint4*)(d_wimg + t * WIMGSZ);
        uint4* dp = (uint4*)(smc + OF_BHI);
        for (int i = idx; i < WIMGSZ / 16; i += 128) dp[i] = sp[i];
    }
    __syncthreads();

    // warp tile: 2x4 warp grid, each warp 32(M) x 64(N)
    int g = lane >> 2, tg = lane & 3;
    int rb = (wid >> 1) * 32, cb = (wid & 1) * 64;
    float c[2][8][4];
    #pragma unroll
    for (int mt = 0; mt < 2; mt++)
        #pragma unroll
        for (int nt = 0; nt < 8; nt++)
            #pragma unroll
            for (int q = 0; q < 4; q++) c[mt][nt][q] = 0.0f;

    #pragma unroll
    for (int p = 0; p < 3; p++) {
        const char* Ab = smc + ((p < 2) ? OF_AHI : OF_ALO);
        const char* Bb = smc + ((p == 1) ? OF_BLO : OF_BHI);
        #pragma unroll
        for (int ks = 0; ks < 8; ks++) {
            int koff = (ks * 16 + tg * 2) * 2;
            unsigned a[2][4], b[8][2];
            #pragma unroll
            for (int mt = 0; mt < 2; mt++) {
                const char* ar = Ab + (rb + mt * 16 + g) * APITCH + koff;
                a[mt][0] = *(const unsigned*)(ar);
                a[mt][1] = *(const unsigned*)(ar + 8 * APITCH);
                a[mt][2] = *(const unsigned*)(ar + 16);
                a[mt][3] = *(const unsigned*)(ar + 8 * APITCH + 16);
            }
            #pragma unroll
            for (int nt = 0; nt < 8; nt++) {
                const char* br = Bb + (cb + nt * 8 + g) * APITCH + koff;
                b[nt][0] = *(const unsigned*)(br);
                b[nt][1] = *(const unsigned*)(br + 16);
            }
            #pragma unroll
            for (int mt = 0; mt < 2; mt++)
                #pragma unroll
                for (int nt = 0; nt < 8; nt++)
                    mma_bf16(c[mt][nt], a[mt], b[nt]);
        }
    }

    // store C fragments to smem
    float* Cb = (float*)(smc + OF_C);
    #pragma unroll
    for (int mt = 0; mt < 2; mt++)
        #pragma unroll
        for (int nt = 0; nt < 8; nt++) {
            int row = rb + mt * 16 + g, col = cb + nt * 8 + tg * 2;
            *(float2*)&Cb[row * CPITCH + col]       = make_float2(c[mt][nt][0], c[mt][nt][1]);
            *(float2*)&Cb[(row + 8) * CPITCH + col] = make_float2(c[mt][nt][2], c[mt][nt][3]);
        }
    __syncthreads();

    // scatter with bias + 1/deg folded
    {
        int r = tid >> 1, c0 = (tid & 1) * 64;
        int d = d_ed[start + r];
        if (d >= 0) {
            float invd = d_inv[d];
            #pragma unroll 4
            for (int j = 0; j < 16; j++) {
                float4 v  = *(float4*)&Cb[r * CPITCH + c0 + 4 * j];
                float4 bb = *(float4*)(smc + OF_BIAS + 4 * (c0 + 4 * j));
                red4(&d_agg[d * HH + c0 + 4 * j],
                     (v.x + bb.x) * invd, (v.y + bb.y) * invd,
                     (v.z + bb.z) * invd, (v.w + bb.w) * invd);
            }
        }
    }
}

// ---------------- GRU kernels (unchanged from R7) ----------------
__global__ __launch_bounds__(128) void k_gi(const float* __restrict__ Wih,
                                            const float* __restrict__ bih) {
    extern __shared__ float sm[];
    float* wt = sm;
    float* Xs = wt + HH * WTS;
    for (int i = threadIdx.x; i < 3 * HH * HH; i += 128) {
        int j = i >> 7, k = i & 127;
        wt[k * WTS + j] = Wih[i];
    }
    int lane = threadIdx.x & 31, w = threadIdx.x >> 5;
    float4 b0 = *(const float4*)&bih[4 * lane];
    float4 b1 = *(const float4*)&bih[128 + 4 * lane];
    float4 b2 = *(const float4*)&bih[256 + 4 * lane];
    __syncthreads();
    float* X = Xs + w * (GNT * HH);
    int gw = blockIdx.x * GNW + w;
    for (int n0 = gw * GNT; n0 < NN; n0 += 148 * GNW * GNT) {
        #pragma unroll
        for (int i = 0; i < GNT; i++)
            *(float4*)&X[i * HH + 4 * lane] = *(const float4*)&d_agg[(n0 + i) * HH + 4 * lane];
        __syncwarp();
        unsigned long long acc[GNT][6];
        #pragma unroll
        for (int i = 0; i < GNT; i++)
            #pragma unroll
            for (int q = 0; q < 6; q++) acc[i][q] = 0ull;
        #pragma unroll 2
        for (int k = 0; k < HH; k++) {
            const float* row = &wt[k * WTS];
            ulonglong2 w0 = *(const ulonglong2*)&row[      4 * lane];
            ulonglong2 w1 = *(const ulonglong2*)&row[128 + 4 * lane];
            ulonglong2 w2 = *(const ulonglong2*)&row[256 + 4 * lane];
            #pragma unroll
            for (int i = 0; i < GNT; i++) {
                unsigned long long xp = pk2(X[i * HH + k]);
                fma2(acc[i][0], xp, w0.x); fma2(acc[i][1], xp, w0.y);
                fma2(acc[i][2], xp, w1.x); fma2(acc[i][3], xp, w1.y);
                fma2(acc[i][4], xp, w2.x); fma2(acc[i][5], xp, w2.y);
            }
        }
        #pragma unroll
        for (int i = 0; i < GNT; i++) {
            float* gp = &d_gi[(n0 + i) * 3 * HH];
            float2 q0 = up2(acc[i][0]), q1 = up2(acc[i][1]), q2 = up2(acc[i][2]);
            float2 q3 = up2(acc[i][3]), q4 = up2(acc[i][4]), q5 = up2(acc[i][5]);
            *(float4*)&gp[      4 * lane] = make_float4(q0.x + b0.x, q0.y + b0.y, q1.x + b0.z, q1.y + b0.w);
            *(float4*)&gp[128 + 4 * lane] = make_float4(q2.x + b1.x, q2.y + b1.y, q3.x + b1.z, q3.y + b1.w);
            *(float4*)&gp[256 + 4 * lane] = make_float4(q4.x + b2.x, q4.y + b2.y, q5.x + b2.z, q5.y + b2.w);
        }
        __syncwarp();
    }
}

__global__ __launch_bounds__(128) void k_gh(const float* __restrict__ Whh,
                                            const float* __restrict__ bhh,
                                            int flip) {
    extern __shared__ float sm[];
    float* wt = sm;
    float* Xs = wt + HH * WTS;
    for (int i = threadIdx.x; i < 3 * HH * HH; i += 128) {
        int j = i >> 7, k = i & 127;
        wt[k * WTS + j] = Whh[i];
    }
    int lane = threadIdx.x & 31, w = threadIdx.x >> 5;
    float4 b0 = *(const float4*)&bhh[4 * lane];
    float4 b1 = *(const float4*)&bhh[128 + 4 * lane];
    float4 b2 = *(const float4*)&bhh[256 + 4 * lane];
    __syncthreads();
    const float* __restrict__ h = flip ? d_hB : d_hA;
    float* __restrict__ hn      = flip ? d_hA : d_hB;
    float* X = Xs + w * (GNT * HH);
    int gw = blockIdx.x * GNW + w;
    for (int n0 = gw * GNT; n0 < NN; n0 += 148 * GNW * GNT) {
        #pragma unroll
        for (int i = 0; i < GNT; i++)
            *(float4*)&X[i * HH + 4 * lane] = *(const float4*)&h[(n0 + i) * HH + 4 * lane];
        __syncwarp();
        unsigned long long acc[GNT][6];
        #pragma unroll
        for (int i = 0; i < GNT; i++)
            #pragma unroll
            for (int q = 0; q < 6; q++) acc[i][q] = 0ull;
        #pragma unroll 2
        for (int k = 0; k < HH; k++) {
            const float* row = &wt[k * WTS];
            ulonglong2 w0 = *(const ulonglong2*)&row[      4 * lane];
            ulonglong2 w1 = *(const ulonglong2*)&row[128 + 4 * lane];
            ulonglong2 w2 = *(const ulonglong2*)&row[256 + 4 * lane];
            #pragma unroll
            for (int i = 0; i < GNT; i++) {
                unsigned long long xp = pk2(X[i * HH + k]);
                fma2(acc[i][0], xp, w0.x); fma2(acc[i][1], xp, w0.y);
                fma2(acc[i][2], xp, w1.x); fma2(acc[i][3], xp, w1.y);
                fma2(acc[i][4], xp, w2.x); fma2(acc[i][5], xp, w2.y);
            }
        }
        #pragma unroll
        for (int i = 0; i < GNT; i++) {
            float2 q0 = up2(acc[i][0]), q1 = up2(acc[i][1]), q2 = up2(acc[i][2]);
            float2 q3 = up2(acc[i][3]), q4 = up2(acc[i][4]), q5 = up2(acc[i][5]);
            float hr0 = q0.x + b0.x, hr1 = q0.y + b0.y, hr2 = q1.x + b0.z, hr3 = q1.y + b0.w;
            float hz0 = q2.x + b1.x, hz1 = q2.y + b1.y, hz2 = q3.x + b1.z, hz3 = q3.y + b1.w;
            float hn0 = q4.x + b2.x, hn1 = q4.y + b2.y, hn2 = q5.x + b2.z, hn3 = q5.y + b2.w;
            const float* gp = &d_gi[(n0 + i) * 3 * HH];
            float4 g0 = *(const float4*)&gp[      4 * lane];
            float4 g1 = *(const float4*)&gp[128 + 4 * lane];
            float4 g2 = *(const float4*)&gp[256 + 4 * lane];
            float4 hh = *(const float4*)&h[(n0 + i) * HH + 4 * lane];
            float4 o;
            { float r = sigf(g0.x + hr0); float z = sigf(g1.x + hz0);
              float nv = tanhf(g2.x + r * hn0); o.x = (1.0f - z) * nv + z * hh.x; }
            { float r = sigf(g0.y + hr1); float z = sigf(g1.y + hz1);
              float nv = tanhf(g2.y + r * hn1); o.y = (1.0f - z) * nv + z * hh.y; }
            { float r = sigf(g0.z + hr2); float z = sigf(g1.z + hz2);
              float nv = tanhf(g2.z + r * hn2); o.z = (1.0f - z) * nv + z * hh.z; }
            { float r = sigf(g0.w + hr3); float z = sigf(g1.w + hz3);
              float nv = tanhf(g2.w + r * hn3); o.w = (1.0f - z) * nv + z * hh.w; }
            *(float4*)&hn[(n0 + i) * HH + 4 * lane] = o;
        }
        __syncwarp();
    }
}

__global__ __launch_bounds__(256) void k_out(const float* __restrict__ W1,
                                             const float* __restrict__ b1,
                                             const float* __restrict__ W2,
                                             const float* __restrict__ b2,
                                             float* __restrict__ out) {
    extern __shared__ float sm[];
    float* Ws = sm;
    float* Xs = sm + 2 * HH * HH;
    for (int i = threadIdx.x; i < 2 * HH * HH / 4; i += 256)
        ((float4*)Ws)[i] = ((const float4*)W1)[i];
    int lane = threadIdx.x & 31, w = threadIdx.x >> 5;
    float4 bb = *(const float4*)&b1[4 * lane];
    float4 w2v = *(const float4*)&W2[4 * lane];
    float b2v = b2[0];
    __syncthreads();
    float* X = Xs + w * (ONT * 2 * 2 * HH);
    int gw = blockIdx.x * ONW + w;
    for (int n0 = gw * ONT; n0 < NN; n0 += 148 * ONW * ONT) {
        #pragma unroll
        for (int i = 0; i < ONT; i++) {
            float4 a = *(const float4*)&d_hA[(n0 + i) * HH + 4 * lane];
            float4 c = *(const float4*)&d_h0[(n0 + i) * HH + 4 * lane];
            float* xr = X + i * 512;
            *(float4*)(xr + 8 * lane)           = make_float4(a.x, a.x, a.y, a.y);
            *(float4*)(xr + 8 * lane + 4)       = make_float4(a.z, a.z, a.w, a.w);
            *(float4*)(xr + 256 + 8 * lane)     = make_float4(c.x, c.x, c.y, c.y);
            *(float4*)(xr + 256 + 8 * lane + 4) = make_float4(c.z, c.z, c.w, c.w);
        }
        __syncwarp();
        unsigned long long acc[ONT][2];
        #pragma unroll
        for (int i = 0; i < ONT; i++) { acc[i][0] = 0ull; acc[i][1] = 0ull; }
        #pragma unroll 4
        for (int k = 0; k < 2 * HH; k++) {
            ulonglong2 wv = *(const ulonglong2*)&Ws[k * HH + 4 * lane];
            #pragma unroll
            for (int i = 0; i < ONT; i++) {
                unsigned long long xk = *(const unsigned long long*)&X[i * 512 + 2 * k];
                fma2(acc[i][0], xk, wv.x);
                fma2(acc[i][1], xk, wv.y);
            }
        }
        #pragma unroll
        for (int i = 0; i < ONT; i++) {
            float2 p0 = up2(acc[i][0]), p1 = up2(acc[i][1]);
            float r0 = fmaxf(p0.x + bb.x, 0.f), r1 = fmaxf(p0.y + bb.y, 0.f);
            float r2 = fmaxf(p1.x + bb.z, 0.f), r3 = fmaxf(p1.y + bb.w, 0.f);
            float p = r0 * w2v.x + r1 * w2v.y + r2 * w2v.z + r3 * w2v.w;
            #pragma unroll
            for (int o = 16; o > 0; o >>= 1) p += __shfl_xor_sync(0xFFFFFFFFu, p, o);
            if (lane == 0) out[n0 + i] = p + b2v;
        }
        __syncwarp();
    }
}

// ---------------- launch ----------------
extern "C" void kernel_launch(void* const* d_in, const int* in_sizes, int n_in,
                              void* d_out, int out_size) {
    (void)in_sizes; (void)n_in; (void)out_size;
    const int*   xidx = (const int*)  d_in[0];
    const float* sel  = (const float*)d_in[1];
    const int*   eidx = (const int*)  d_in[2];
    const int*   et   = (const int*)  d_in[3];
    const int*   epos = (const int*)  d_in[4];
    const float* emb  = (const float*)d_in[5];
    const float* pe   = (const float*)d_in[6];
    const float* Wg   = (const float*)d_in[7];
    const float* bg   = (const float*)d_in[8];
    const float* Wt   = (const float*)d_in[9];
    const float* bt   = (const float*)d_in[10];
    const float* Wih  = (const float*)d_in[11];
    const float* Whh  = (const float*)d_in[12];
    const float* bih  = (const float*)d_in[13];
    const float* bhh  = (const float*)d_in[14];
    const float* W1   = (const float*)d_in[15];
    const float* b1   = (const float*)d_in[16];
    const float* W2   = (const float*)d_in[17];
    const float* b2   = (const float*)d_in[18];
    float* out = (float*)d_out;
    const int* src = eidx;
    const int* dst = eidx + EE;

    const int SM_GRU = (HH * WTS + GNW * GNT * HH) * 4;
    const int SM_OUT = (2 * HH * HH + ONW * ONT * 2 * 2 * HH) * 4;

    cudaFuncSetAttribute(k_edge, cudaFuncAttributeMaxDynamicSharedMemorySize, SM_EDGE_BYTES);
    cudaFuncSetAttribute(k_gi,   cudaFuncAttributeMaxDynamicSharedMemorySize, SM_GRU);
    cudaFuncSetAttribute(k_gh,   cudaFuncAttributeMaxDynamicSharedMemorySize, SM_GRU);
    cudaFuncSetAttribute(k_out,  cudaFuncAttributeMaxDynamicSharedMemorySize, SM_OUT);

    k_init_pad<<<(PADE + 255) / 256, 256>>>();
    k_hist<<<(EE + 255) / 256, 256>>>(et);
    k_off<<<1, 1>>>();
    k_perm<<<(EE + 255) / 256, 256>>>(src, dst, et, epos);
    k_zero_cnt<<<(NN + 255) / 256, 256>>>();
    k_h0<<<(NN * 32 + 255) / 256, 256>>>(xidx, sel, emb);
    k_deg<<<(EE + 255) / 256, 256>>>(dst);
    k_inv<<<(NN + 255) / 256, 256>>>();
    k_gtab<<<NPOS, 128>>>(pe, Wg, bg);
    k_wimg<<<NT, 256>>>(Wt);

    for (int it = 0; it < GITERS; it++) {
        int flip = it & 1;
        k_zero_agg<<<(NN * HH / 4 + 255) / 256, 256>>>();
        k_edge<<<PADE / EPB, 256, SM_EDGE_BYTES>>>(bt, flip);
        k_gi<<<148, 128, SM_GRU>>>(Wih, bih);
        k_gh<<<148, 128, SM_GRU>>>(Whh, bhh, flip);
    }
    k_out<<<148, 256, SM_OUT>>>(W1, b1, W2, b2, out);
}

// round 11
// speedup vs baseline: 1.6191x; 1.3467x over previous
#include <cuda_runtime.h>
#include <math.h>
#include <stdint.h>

#define NN   100000
#define EE   640000
#define HH   128
#define EMBD 96
#define SELD 32
#define PDIM 64
#define NPOS 513
#define NT   3
#define GITERS 6

#define EPB  128
#define PADE (EE + NT*EPB)

#define ONW 8
#define ONT 4

// k_edge smem layout (bytes)
#define OF_BIAS 0
#define OF_AHI  512
#define OF_ALO  35328
#define OF_BHI  70144
#define OF_BLO  104960
#define OF_C    139776
#define SM_EDGE_BYTES 207360
#define APITCH  272            // 136 bf16 per row
#define CPITCH  132            // floats
#define WIMGSZ  69632          // per-type [hi 34816][lo 34816]

// k_gemm384 (GRU HMMA) smem layout
#define NBX     782            // ceil(NN/128)
#define GHALF   192
#define IMGSEC  (384*APITCH)   // 104448 per hi/lo section
#define OFG_BIAS 0
#define OFG_AHI  768
#define OFG_ALO  35584
#define OFG_BHI  70400
#define OFG_BLO  122624
#define SM_G384  174848

// ---------------- device scratch ----------------
__device__ float d_h0 [NN * HH];
__device__ float d_hA [NN * HH];
__device__ float d_hB [NN * HH];
__device__ float d_agg[NN * HH];
__device__ float d_gi [NN * 3 * HH];
__device__ float d_gh [NN * 3 * HH];
__device__ float d_gtab[NPOS * HH];
__device__ float d_cnt[NN];
__device__ float d_inv[NN];
__device__ int   d_es[PADE];
__device__ int   d_ed[PADE];
__device__ int   d_ps[PADE];
__device__ int   d_tcnt[NT];
__device__ int   d_cur[NT];
__device__ int   d_base[NT + 1];
__device__ unsigned char d_wimg[NT * WIMGSZ];        // edge W^T images
__device__ unsigned char d_gruimg[2 * 2 * IMGSEC];   // [ih|hh][hi|lo] pitched W images

__device__ __forceinline__ float sigf(float x) { return 1.0f / (1.0f + __expf(-x)); }

// ---- packed helpers ----
__device__ __forceinline__ void fma2(unsigned long long& d, unsigned long long a,
                                     unsigned long long b) {
    asm("fma.rn.f32x2 %0, %1, %2, %0;" : "+l"(d) : "l"(a), "l"(b));
}
__device__ __forceinline__ float2 up2(unsigned long long v) {
    float2 r;
    asm("mov.b64 {%0, %1}, %2;" : "=f"(r.x), "=f"(r.y) : "l"(v));
    return r;
}
__device__ __forceinline__ void red4(float* p, float a, float b, float c, float d) {
    asm volatile("red.global.add.v4.f32 [%0], {%1, %2, %3, %4};"
                 :: "l"(p), "f"(a), "f"(b), "f"(c), "f"(d) : "memory");
}
__device__ __forceinline__ unsigned pkbf(float x, float y) {
    unsigned r;
    asm("cvt.rn.bf16x2.f32 %0, %1, %2;" : "=r"(r) : "f"(y), "f"(x));
    return r;
}
__device__ __forceinline__ void split2(float x, float y, unsigned& hi, unsigned& lo) {
    hi = pkbf(x, y);
    float xh = __uint_as_float(hi << 16);
    float yh = __uint_as_float(hi & 0xffff0000u);
    lo = pkbf(x - xh, y - yh);
}
__device__ __forceinline__ void mma_bf16(float c[4], const unsigned a[4], const unsigned b[2]) {
    asm volatile("mma.sync.aligned.m16n8k16.row.col.f32.bf16.bf16.f32 "
                 "{%0,%1,%2,%3}, {%4,%5,%6,%7}, {%8,%9}, {%0,%1,%2,%3};"
                 : "+f"(c[0]), "+f"(c[1]), "+f"(c[2]), "+f"(c[3])
                 : "r"(a[0]), "r"(a[1]), "r"(a[2]), "r"(a[3]), "r"(b[0]), "r"(b[1]));
}

// ---------------- setup kernels ----------------
__global__ void k_init_pad() {
    int i = blockIdx.x * blockDim.x + threadIdx.x;
    if (i < PADE) { d_ed[i] = -1; d_es[i] = 0; d_ps[i] = 0; }
    if (i < NT) { d_tcnt[i] = 0; d_cur[i] = 0; }
}
__global__ void k_hist(const int* __restrict__ et) {
    __shared__ int sc[NT];
    if (threadIdx.x < NT) sc[threadIdx.x] = 0;
    __syncthreads();
    int e = blockIdx.x * blockDim.x + threadIdx.x;
    if (e < EE) atomicAdd(&sc[et[e]], 1);
    __syncthreads();
    if (threadIdx.x < NT) atomicAdd(&d_tcnt[threadIdx.x], sc[threadIdx.x]);
}
__global__ void k_off() {
    int b = 0;
    for (int t = 0; t < NT; t++) {
        d_base[t] = b;
        b += ((d_tcnt[t] + EPB - 1) / EPB) * EPB;
    }
    d_base[NT] = b;
}
__global__ void k_perm(const int* __restrict__ src, const int* __restrict__ dst,
                       const int* __restrict__ et, const int* __restrict__ epos) {
    __shared__ int s_cnt[NT], s_base[NT];
    if (threadIdx.x < NT) s_cnt[threadIdx.x] = 0;
    __syncthreads();
    int e = blockIdx.x * blockDim.x + threadIdx.x;
    int t = 0, lr = 0;
    if (e < EE) { t = et[e]; lr = atomicAdd(&s_cnt[t], 1); }
    __syncthreads();
    if (threadIdx.x < NT) s_base[threadIdx.x] = atomicAdd(&d_cur[threadIdx.x], s_cnt[threadIdx.x]);
    __syncthreads();
    if (e < EE) {
        int p = d_base[t] + s_base[t] + lr;
        d_es[p] = src[e]; d_ed[p] = dst[e]; d_ps[p] = epos[e];
    }
}
__global__ void k_zero_cnt() {
    int i = blockIdx.x * blockDim.x + threadIdx.x;
    if (i < NN) d_cnt[i] = 0.0f;
}
__global__ void k_h0(const int* __restrict__ xidx, const float* __restrict__ sel,
                     const float* __restrict__ emb) {
    int t = blockIdx.x * blockDim.x + threadIdx.x;
    if (t >= NN * 32) return;
    int n = t >> 5, q = (t & 31) * 4;
    float4 v;
    if (q < EMBD) v = *(const float4*)&emb[(long long)xidx[n] * EMBD + q];
    else          v = *(const float4*)&sel[n * SELD + (q - EMBD)];
    *(float4*)&d_h0[n * HH + q] = v;
    *(float4*)&d_hA[n * HH + q] = v;
}
__global__ void k_deg(const int* __restrict__ dst) {
    int e = blockIdx.x * blockDim.x + threadIdx.x;
    if (e < EE) atomicAdd(&d_cnt[dst[e]], 1.0f);
}
__global__ void k_inv() {
    int i = blockIdx.x * blockDim.x + threadIdx.x;
    if (i < NN) d_inv[i] = 1.0f / fmaxf(d_cnt[i], 1.0f);
}
__global__ void k_zero_agg() {
    int i = blockIdx.x * blockDim.x + threadIdx.x;
    if (i < NN * HH / 4) ((float4*)d_agg)[i] = make_float4(0.f, 0.f, 0.f, 0.f);
}
__global__ __launch_bounds__(128) void k_gtab(const float* __restrict__ pe,
                                              const float* __restrict__ Wg,
                                              const float* __restrict__ bg) {
    __shared__ float ps[PDIM];
    int p = blockIdx.x;
    if (threadIdx.x < PDIM) ps[threadIdx.x] = pe[p * PDIM + threadIdx.x];
    __syncthreads();
    int j = threadIdx.x;
    float a = 0.0f;
    #pragma unroll 8
    for (int k = 0; k < PDIM; k++) a += ps[k] * Wg[k * HH + j];
    d_gtab[p * HH + j] = 2.0f * sigf(a + bg[j]);
}
// edge W^T images
__global__ void k_wimg(const float* __restrict__ Wt) {
    int t = blockIdx.x;
    unsigned char* wh = d_wimg + t * WIMGSZ;
    unsigned char* wl = wh + 34816;
    for (int i = threadIdx.x; i < 128 * 64; i += blockDim.x) {
        int n = i >> 6, k = (i & 63) * 2;
        float v0 = Wt[t * HH * HH + k * HH + n];
        float v1 = Wt[t * HH * HH + (k + 1) * HH + n];
        unsigned hi, lo;
        split2(v0, v1, hi, lo);
        int o = n * APITCH + k * 2;
        *(unsigned*)(wh + o) = hi;
        *(unsigned*)(wl + o) = lo;
    }
}
// GRU weight images: W is [384,128] row-major, already B[n=j][k]; pitched split
__global__ void k_wgru(const float* __restrict__ Wih, const float* __restrict__ Whh) {
    int m = blockIdx.y;
    const float* W = m ? Whh : Wih;
    unsigned char* wh = d_gruimg + m * 2 * IMGSEC;
    unsigned char* wl = wh + IMGSEC;
    for (int i = blockIdx.x * blockDim.x + threadIdx.x; i < 384 * 64; i += gridDim.x * blockDim.x) {
        int j = i >> 6, k = (i & 63) * 2;
        unsigned hi, lo;
        split2(W[j * 128 + k], W[j * 128 + k + 1], hi, lo);
        int o = j * APITCH + k * 2;
        *(unsigned*)(wh + o) = hi;
        *(unsigned*)(wl + o) = lo;
    }
}

// ---------------- edge phase: HMMA bf16x3 GEMM per 128-edge tile (unchanged R10) ----------------
__global__ __launch_bounds__(256) void k_edge(const float* __restrict__ bt, int flip) {
    extern __shared__ char smc[];
    int tid = threadIdx.x, wid = tid >> 5, lane = tid & 31;
    const float* __restrict__ h = flip ? d_hB : d_hA;
    int start = blockIdx.x * EPB;
    int t = (start >= d_base[1]) + (start >= d_base[2]);

    if (tid < 128) {
        *(float*)(smc + OF_BIAS + 4 * tid) = bt[t * HH + tid];
        int r = tid;
        int s = d_es[start + r], pp = d_ps[start + r];
        const float4* hv = (const float4*)&h[s * HH];
        const float4* gv = (const float4*)&d_gtab[pp * HH];
        char* arh = smc + OF_AHI + r * APITCH;
        char* arl = smc + OF_ALO + r * APITCH;
        #pragma unroll 8
        for (int i = 0; i < 32; i++) {
            float4 a = hv[i], gg = gv[i];
            unsigned h0, l0, h1, l1;
            split2(a.x * gg.x, a.y * gg.y, h0, l0);
            split2(a.z * gg.z, a.w * gg.w, h1, l1);
            *(uint2*)(arh + i * 8) = make_uint2(h0, h1);
            *(uint2*)(arl + i * 8) = make_uint2(l0, l1);
        }
    } else {
        int idx = tid - 128;
        const uint4* sp = (const uint4*)(d_wimg + t * WIMGSZ);
        uint4* dp = (uint4*)(smc + OF_BHI);
        for (int i = idx; i < WIMGSZ / 16; i += 128) dp[i] = sp[i];
    }
    __syncthreads();

    int g = lane >> 2, tg = lane & 3;
    int rb = (wid >> 1) * 32, cb = (wid & 1) * 64;
    float c[2][8][4];
    #pragma unroll
    for (int mt = 0; mt < 2; mt++)
        #pragma unroll
        for (int nt = 0; nt < 8; nt++)
            #pragma unroll
            for (int q = 0; q < 4; q++) c[mt][nt][q] = 0.0f;

    #pragma unroll
    for (int p = 0; p < 3; p++) {
        const char* Ab = smc + ((p < 2) ? OF_AHI : OF_ALO);
        const char* Bb = smc + ((p == 1) ? OF_BLO : OF_BHI);
        #pragma unroll
        for (int ks = 0; ks < 8; ks++) {
            int koff = (ks * 16 + tg * 2) * 2;
            unsigned a[2][4], b[8][2];
            #pragma unroll
            for (int mt = 0; mt < 2; mt++) {
                const char* ar = Ab + (rb + mt * 16 + g) * APITCH + koff;
                a[mt][0] = *(const unsigned*)(ar);
                a[mt][1] = *(const unsigned*)(ar + 8 * APITCH);
                a[mt][2] = *(const unsigned*)(ar + 16);
                a[mt][3] = *(const unsigned*)(ar + 8 * APITCH + 16);
            }
            #pragma unroll
            for (int nt = 0; nt < 8; nt++) {
                const char* br = Bb + (cb + nt * 8 + g) * APITCH + koff;
                b[nt][0] = *(const unsigned*)(br);
                b[nt][1] = *(const unsigned*)(br + 16);
            }
            #pragma unroll
            for (int mt = 0; mt < 2; mt++)
                #pragma unroll
                for (int nt = 0; nt < 8; nt++)
                    mma_bf16(c[mt][nt], a[mt], b[nt]);
        }
    }

    float* Cb = (float*)(smc + OF_C);
    #pragma unroll
    for (int mt = 0; mt < 2; mt++)
        #pragma unroll
        for (int nt = 0; nt < 8; nt++) {
            int row = rb + mt * 16 + g, col = cb + nt * 8 + tg * 2;
            *(float2*)&Cb[row * CPITCH + col]       = make_float2(c[mt][nt][0], c[mt][nt][1]);
            *(float2*)&Cb[(row + 8) * CPITCH + col] = make_float2(c[mt][nt][2], c[mt][nt][3]);
        }
    __syncthreads();

    {
        int r = tid >> 1, c0 = (tid & 1) * 64;
        int d = d_ed[start + r];
        if (d >= 0) {
            float invd = d_inv[d];
            #pragma unroll 4
            for (int j = 0; j < 16; j++) {
                float4 v  = *(float4*)&Cb[r * CPITCH + c0 + 4 * j];
                float4 bb = *(float4*)(smc + OF_BIAS + 4 * (c0 + 4 * j));
                red4(&d_agg[d * HH + c0 + 4 * j],
                     (v.x + bb.x) * invd, (v.y + bb.y) * invd,
                     (v.z + bb.z) * invd, (v.w + bb.w) * invd);
            }
        }
    }
}

// ---------------- GRU GEMM: C[128,384-half] = A[128,128] @ W^T, HMMA bf16x3 ----------------
// which=0: A=d_agg -> d_gi (W_ih); which=1: A=h -> d_gh (W_hh). Bias folded.
__global__ __launch_bounds__(256) void k_gemm384(const float* __restrict__ bias,
                                                 int which, int flip) {
    extern __shared__ char smc[];
    int tid = threadIdx.x, wid = tid >> 5, lane = tid & 31;
    int n0 = blockIdx.x * 128;
    int half = blockIdx.y;
    const float* __restrict__ A = which ? (flip ? d_hB : d_hA) : d_agg;
    float* __restrict__ Out = which ? d_gh : d_gi;
    const unsigned char* img = d_gruimg + which * 2 * IMGSEC;

    if (tid < GHALF) *(float*)(smc + OFG_BIAS + 4 * tid) = bias[half * GHALF + tid];

    if (tid < 128) {
        int r = tid, n = n0 + r;
        char* arh = smc + OFG_AHI + r * APITCH;
        char* arl = smc + OFG_ALO + r * APITCH;
        if (n < NN) {
            const float4* av = (const float4*)&A[n * HH];
            #pragma unroll 8
            for (int i = 0; i < 32; i++) {
                float4 a = av[i];
                unsigned h0, l0, h1, l1;
                split2(a.x, a.y, h0, l0);
                split2(a.z, a.w, h1, l1);
                *(uint2*)(arh + i * 8) = make_uint2(h0, h1);
                *(uint2*)(arl + i * 8) = make_uint2(l0, l1);
            }
        } else {
            #pragma unroll 8
            for (int i = 0; i < 32; i++) {
                *(uint2*)(arh + i * 8) = make_uint2(0u, 0u);
                *(uint2*)(arl + i * 8) = make_uint2(0u, 0u);
            }
        }
    } else {
        int idx = tid - 128;
        const uint4* sph = (const uint4*)(img + half * GHALF * APITCH);
        const uint4* spl = (const uint4*)(img + IMGSEC + half * GHALF * APITCH);
        uint4* dph = (uint4*)(smc + OFG_BHI);
        uint4* dpl = (uint4*)(smc + OFG_BLO);
        for (int i = idx; i < GHALF * APITCH / 16; i += 128) { dph[i] = sph[i]; dpl[i] = spl[i]; }
    }
    __syncthreads();

    int g = lane >> 2, tg = lane & 3;
    int rb = (wid & 3) * 32, cb = (wid >> 2) * 96;
    float c[2][12][4];
    #pragma unroll
    for (int mt = 0; mt < 2; mt++)
        #pragma unroll
        for (int nt = 0; nt < 12; nt++)
            #pragma unroll
            for (int q = 0; q < 4; q++) c[mt][nt][q] = 0.0f;

    #pragma unroll
    for (int p = 0; p < 3; p++) {
        const char* Ab = smc + ((p < 2) ? OFG_AHI : OFG_ALO);
        const char* Bb = smc + ((p == 1) ? OFG_BLO : OFG_BHI);
        #pragma unroll
        for (int ks = 0; ks < 8; ks++) {
            int koff = (ks * 16 + tg * 2) * 2;
            unsigned a[2][4], b[12][2];
            #pragma unroll
            for (int mt = 0; mt < 2; mt++) {
                const char* ar = Ab + (rb + mt * 16 + g) * APITCH + koff;
                a[mt][0] = *(const unsigned*)(ar);
                a[mt][1] = *(const unsigned*)(ar + 8 * APITCH);
                a[mt][2] = *(const unsigned*)(ar + 16);
                a[mt][3] = *(const unsigned*)(ar + 8 * APITCH + 16);
            }
            #pragma unroll
            for (int nt = 0; nt < 12; nt++) {
                const char* br = Bb + (cb + nt * 8 + g) * APITCH + koff;
                b[nt][0] = *(const unsigned*)(br);
                b[nt][1] = *(const unsigned*)(br + 16);
            }
            #pragma unroll
            for (int mt = 0; mt < 2; mt++)
                #pragma unroll
                for (int nt = 0; nt < 12; nt++)
                    mma_bf16(c[mt][nt], a[mt], b[nt]);
        }
    }

    // store with bias folded, direct to global [n, 384]
    #pragma unroll
    for (int mt = 0; mt < 2; mt++) {
        int row = rb + mt * 16 + g;
        int n1 = n0 + row, n2 = n1 + 8;
        #pragma unroll
        for (int nt = 0; nt < 12; nt++) {
            int col = cb + nt * 8 + tg * 2;
            float2 bb = *(float2*)(smc + OFG_BIAS + 4 * col);
            int gcol = half * GHALF + col;
            if (n1 < NN)
                *(float2*)&Out[n1 * 384 + gcol] = make_float2(c[mt][nt][0] + bb.x, c[mt][nt][1] + bb.y);
            if (n2 < NN)
                *(float2*)&Out[n2 * 384 + gcol] = make_float2(c[mt][nt][2] + bb.x, c[mt][nt][3] + bb.y);
        }
    }
}

// ---------------- GRU elementwise combine ----------------
__global__ void k_comb(int flip) {
    const float* __restrict__ h = flip ? d_hB : d_hA;
    float* __restrict__ hn      = flip ? d_hA : d_hB;
    int t = blockIdx.x * blockDim.x + threadIdx.x;
    if (t >= NN * 32) return;
    int n = t >> 5, q = (t & 31) * 4;
    const float* gp = &d_gi[n * 384];
    const float* mp = &d_gh[n * 384];
    float4 g0 = *(const float4*)&gp[q];
    float4 g1 = *(const float4*)&gp[128 + q];
    float4 g2 = *(const float4*)&gp[256 + q];
    float4 m0 = *(const float4*)&mp[q];
    float4 m1 = *(const float4*)&mp[128 + q];
    float4 m2 = *(const float4*)&mp[256 + q];
    float4 hh = *(const float4*)&h[n * HH + q];
    float4 o;
    { float r = sigf(g0.x + m0.x); float z = sigf(g1.x + m1.x);
      float nv = tanhf(g2.x + r * m2.x); o.x = (1.0f - z) * nv + z * hh.x; }
    { float r = sigf(g0.y + m0.y); float z = sigf(g1.y + m1.y);
      float nv = tanhf(g2.y + r * m2.y); o.y = (1.0f - z) * nv + z * hh.y; }
    { float r = sigf(g0.z + m0.z); float z = sigf(g1.z + m1.z);
      float nv = tanhf(g2.z + r * m2.z); o.z = (1.0f - z) * nv + z * hh.z; }
    { float r = sigf(g0.w + m0.w); float z = sigf(g1.w + m1.w);
      float nv = tanhf(g2.w + r * m2.w); o.w = (1.0f - z) * nv + z * hh.w; }
    *(float4*)&hn[n * HH + q] = o;
}

// ---------------- output (unchanged R10) ----------------
__global__ __launch_bounds__(256) void k_out(const float* __restrict__ W1,
                                             const float* __restrict__ b1,
                                             const float* __restrict__ W2,
                                             const float* __restrict__ b2,
                                             float* __restrict__ out) {
    extern __shared__ float sm[];
    float* Ws = sm;
    float* Xs = sm + 2 * HH * HH;
    for (int i = threadIdx.x; i < 2 * HH * HH / 4; i += 256)
        ((float4*)Ws)[i] = ((const float4*)W1)[i];
    int lane = threadIdx.x & 31, w = threadIdx.x >> 5;
    float4 bb = *(const float4*)&b1[4 * lane];
    float4 w2v = *(const float4*)&W2[4 * lane];
    float b2v = b2[0];
    __syncthreads();
    float* X = Xs + w * (ONT * 2 * 2 * HH);
    int gw = blockIdx.x * ONW + w;
    for (int n0 = gw * ONT; n0 < NN; n0 += 148 * ONW * ONT) {
        #pragma unroll
        for (int i = 0; i < ONT; i++) {
            float4 a = *(const float4*)&d_hA[(n0 + i) * HH + 4 * lane];
            float4 c = *(const float4*)&d_h0[(n0 + i) * HH + 4 * lane];
            float* xr = X + i * 512;
            *(float4*)(xr + 8 * lane)           = make_float4(a.x, a.x, a.y, a.y);
            *(float4*)(xr + 8 * lane + 4)       = make_float4(a.z, a.z, a.w, a.w);
            *(float4*)(xr + 256 + 8 * lane)     = make_float4(c.x, c.x, c.y, c.y);
            *(float4*)(xr + 256 + 8 * lane + 4) = make_float4(c.z, c.z, c.w, c.w);
        }
        __syncwarp();
        unsigned long long acc[ONT][2];
        #pragma unroll
        for (int i = 0; i < ONT; i++) { acc[i][0] = 0ull; acc[i][1] = 0ull; }
        #pragma unroll 4
        for (int k = 0; k < 2 * HH; k++) {
            ulonglong2 wv = *(const ulonglong2*)&Ws[k * HH + 4 * lane];
            #pragma unroll
            for (int i = 0; i < ONT; i++) {
                unsigned long long xk = *(const unsigned long long*)&X[i * 512 + 2 * k];
                fma2(acc[i][0], xk, wv.x);
                fma2(acc[i][1], xk, wv.y);
            }
        }
        #pragma unroll
        for (int i = 0; i < ONT; i++) {
            float2 p0 = up2(acc[i][0]), p1 = up2(acc[i][1]);
            float r0 = fmaxf(p0.x + bb.x, 0.f), r1 = fmaxf(p0.y + bb.y, 0.f);
            float r2 = fmaxf(p1.x + bb.z, 0.f), r3 = fmaxf(p1.y + bb.w, 0.f);
            float p = r0 * w2v.x + r1 * w2v.y + r2 * w2v.z + r3 * w2v.w;
            #pragma unroll
            for (int o = 16; o > 0; o >>= 1) p += __shfl_xor_sync(0xFFFFFFFFu, p, o);
            if (lane == 0) out[n0 + i] = p + b2v;
        }
        __syncwarp();
    }
}

// ---------------- launch ----------------
extern "C" void kernel_launch(void* const* d_in, const int* in_sizes, int n_in,
                              void* d_out, int out_size) {
    (void)in_sizes; (void)n_in; (void)out_size;
    const int*   xidx = (const int*)  d_in[0];
    const float* sel  = (const float*)d_in[1];
    const int*   eidx = (const int*)  d_in[2];
    const int*   et   = (const int*)  d_in[3];
    const int*   epos = (const int*)  d_in[4];
    const float* emb  = (const float*)d_in[5];
    const float* pe   = (const float*)d_in[6];
    const float* Wg   = (const float*)d_in[7];
    const float* bg   = (const float*)d_in[8];
    const float* Wt   = (const float*)d_in[9];
    const float* bt   = (const float*)d_in[10];
    const float* Wih  = (const float*)d_in[11];
    const float* Whh  = (const float*)d_in[12];
    const float* bih  = (const float*)d_in[13];
    const float* bhh  = (const float*)d_in[14];
    const float* W1   = (const float*)d_in[15];
    const float* b1   = (const float*)d_in[16];
    const float* W2   = (const float*)d_in[17];
    const float* b2   = (const float*)d_in[18];
    float* out = (float*)d_out;
    const int* src = eidx;
    const int* dst = eidx + EE;

    const int SM_OUT = (2 * HH * HH + ONW * ONT * 2 * 2 * HH) * 4;

    cudaFuncSetAttribute(k_edge,    cudaFuncAttributeMaxDynamicSharedMemorySize, SM_EDGE_BYTES);
    cudaFuncSetAttribute(k_gemm384, cudaFuncAttributeMaxDynamicSharedMemorySize, SM_G384);
    cudaFuncSetAttribute(k_out,     cudaFuncAttributeMaxDynamicSharedMemorySize, SM_OUT);

    k_init_pad<<<(PADE + 255) / 256, 256>>>();
    k_hist<<<(EE + 255) / 256, 256>>>(et);
    k_off<<<1, 1>>>();
    k_perm<<<(EE + 255) / 256, 256>>>(src, dst, et, epos);
    k_zero_cnt<<<(NN + 255) / 256, 256>>>();
    k_h0<<<(NN * 32 + 255) / 256, 256>>>(xidx, sel, emb);
    k_deg<<<(EE + 255) / 256, 256>>>(dst);
    k_inv<<<(NN + 255) / 256, 256>>>();
    k_gtab<<<NPOS, 128>>>(pe, Wg, bg);
    k_wimg<<<NT, 256>>>(Wt);
    k_wgru<<<dim3(96, 2), 256>>>(Wih, Whh);

    dim3 ggrid(NBX, 2);
    for (int it = 0; it < GITERS; it++) {
        int flip = it & 1;
        k_zero_agg<<<(NN * HH / 4 + 255) / 256, 256>>>();
        k_edge<<<PADE / EPB, 256, SM_EDGE_BYTES>>>(bt, flip);
        k_gemm384<<<ggrid, 256, SM_G384>>>(bih, 0, flip);
        k_gemm384<<<ggrid, 256, SM_G384>>>(bhh, 1, flip);
        k_comb<<<(NN * 32 + 255) / 256, 256>>>(flip);
    }
    k_out<<<148, 256, SM_OUT>>>(W1, b1, W2, b2, out);
}

// round 12
// speedup vs baseline: 1.6227x; 1.0022x over previous
#include <cuda_runtime.h>
#include <math.h>
#include <stdint.h>

#define NN   100000
#define EE   640000
#define HH   128
#define EMBD 96
#define SELD 32
#define PDIM 64
#define NPOS 513
#define NT   3
#define GITERS 6

#define EPB  128
#define PADE (EE + NT*EPB)

#define ONW 8
#define ONT 4

// k_edge smem layout (bytes)
#define OF_BIAS 0
#define OF_AHI  512
#define OF_ALO  35328
#define OF_BHI  70144
#define OF_BLO  104960
#define OF_C    139776
#define SM_EDGE_BYTES 207360
#define APITCH  272            // 136 bf16 per row
#define CPITCH  132            // floats
#define WIMGSZ  69632          // per-type [hi 34816][lo 34816]

// k_gemm384 (GRU HMMA) smem layout
#define NBX     782            // ceil(NN/128)
#define GHALF   192
#define IMGSEC  (384*APITCH)   // 104448 per hi/lo section
#define OFG_BIAS 0
#define OFG_AHI  768
#define OFG_ALO  35584
#define OFG_BHI  70400
#define OFG_BLO  122624
#define SM_G384  174848

// ---------------- device scratch ----------------
__device__ float d_h0 [NN * HH];
__device__ float d_hA [NN * HH];
__device__ float d_hB [NN * HH];
__device__ float d_agg[NN * HH];
__device__ float d_gi [NN * 3 * HH];
__device__ float d_gh [NN * 3 * HH];
__device__ float d_gtab[NPOS * HH];
__device__ float d_cnt[NN];
__device__ float d_inv[NN];
__device__ int   d_es[PADE];
__device__ int   d_ed[PADE];
__device__ int   d_ps[PADE];
__device__ int   d_tcnt[NT];
__device__ int   d_cur[NT];
__device__ int   d_base[NT + 1];
__device__ unsigned char d_wimg[NT * WIMGSZ];        // edge W^T images
__device__ unsigned char d_gruimg[2 * 2 * IMGSEC];   // [ih|hh][hi|lo] pitched W images

__device__ __forceinline__ float sigf(float x) { return 1.0f / (1.0f + __expf(-x)); }

// ---- packed helpers ----
__device__ __forceinline__ void fma2(unsigned long long& d, unsigned long long a,
                                     unsigned long long b) {
    asm("fma.rn.f32x2 %0, %1, %2, %0;" : "+l"(d) : "l"(a), "l"(b));
}
__device__ __forceinline__ float2 up2(unsigned long long v) {
    float2 r;
    asm("mov.b64 {%0, %1}, %2;" : "=f"(r.x), "=f"(r.y) : "l"(v));
    return r;
}
__device__ __forceinline__ void red4(float* p, float a, float b, float c, float d) {
    asm volatile("red.global.add.v4.f32 [%0], {%1, %2, %3, %4};"
                 :: "l"(p), "f"(a), "f"(b), "f"(c), "f"(d) : "memory");
}
__device__ __forceinline__ unsigned pkbf(float x, float y) {
    unsigned r;
    asm("cvt.rn.bf16x2.f32 %0, %1, %2;" : "=r"(r) : "f"(y), "f"(x));
    return r;
}
__device__ __forceinline__ void split2(float x, float y, unsigned& hi, unsigned& lo) {
    hi = pkbf(x, y);
    float xh = __uint_as_float(hi << 16);
    float yh = __uint_as_float(hi & 0xffff0000u);
    lo = pkbf(x - xh, y - yh);
}
__device__ __forceinline__ void mma_bf16(float c[4], const unsigned a[4], const unsigned b[2]) {
    asm volatile("mma.sync.aligned.m16n8k16.row.col.f32.bf16.bf16.f32 "
                 "{%0,%1,%2,%3}, {%4,%5,%6,%7}, {%8,%9}, {%0,%1,%2,%3};"
                 : "+f"(c[0]), "+f"(c[1]), "+f"(c[2]), "+f"(c[3])
                 : "r"(a[0]), "r"(a[1]), "r"(a[2]), "r"(a[3]), "r"(b[0]), "r"(b[1]));
}

// ---------------- setup kernels ----------------
__global__ void k_init_pad() {
    int i = blockIdx.x * blockDim.x + threadIdx.x;
    if (i < PADE) { d_ed[i] = -1; d_es[i] = 0; d_ps[i] = 0; }
    if (i < NT) { d_tcnt[i] = 0; d_cur[i] = 0; }
}
__global__ void k_hist(const int* __restrict__ et) {
    __shared__ int sc[NT];
    if (threadIdx.x < NT) sc[threadIdx.x] = 0;
    __syncthreads();
    int e = blockIdx.x * blockDim.x + threadIdx.x;
    if (e < EE) atomicAdd(&sc[et[e]], 1);
    __syncthreads();
    if (threadIdx.x < NT) atomicAdd(&d_tcnt[threadIdx.x], sc[threadIdx.x]);
}
__global__ void k_off() {
    int b = 0;
    for (int t = 0; t < NT; t++) {
        d_base[t] = b;
        b += ((d_tcnt[t] + EPB - 1) / EPB) * EPB;
    }
    d_base[NT] = b;
}
__global__ void k_perm(const int* __restrict__ src, const int* __restrict__ dst,
                       const int* __restrict__ et, const int* __restrict__ epos) {
    __shared__ int s_cnt[NT], s_base[NT];
    if (threadIdx.x < NT) s_cnt[threadIdx.x] = 0;
    __syncthreads();
    int e = blockIdx.x * blockDim.x + threadIdx.x;
    int t = 0, lr = 0;
    if (e < EE) { t = et[e]; lr = atomicAdd(&s_cnt[t], 1); }
    __syncthreads();
    if (threadIdx.x < NT) s_base[threadIdx.x] = atomicAdd(&d_cur[threadIdx.x], s_cnt[threadIdx.x]);
    __syncthreads();
    if (e < EE) {
        int p = d_base[t] + s_base[t] + lr;
        d_es[p] = src[e]; d_ed[p] = dst[e]; d_ps[p] = epos[e];
    }
}
__global__ void k_zero_cnt() {
    int i = blockIdx.x * blockDim.x + threadIdx.x;
    if (i < NN) d_cnt[i] = 0.0f;
}
__global__ void k_h0(const int* __restrict__ xidx, const float* __restrict__ sel,
                     const float* __restrict__ emb) {
    int t = blockIdx.x * blockDim.x + threadIdx.x;
    if (t >= NN * 32) return;
    int n = t >> 5, q = (t & 31) * 4;
    float4 v;
    if (q < EMBD) v = *(const float4*)&emb[(long long)xidx[n] * EMBD + q];
    else          v = *(const float4*)&sel[n * SELD + (q - EMBD)];
    *(float4*)&d_h0[n * HH + q] = v;
    *(float4*)&d_hA[n * HH + q] = v;
}
__global__ void k_deg(const int* __restrict__ dst) {
    int e = blockIdx.x * blockDim.x + threadIdx.x;
    if (e < EE) atomicAdd(&d_cnt[dst[e]], 1.0f);
}
__global__ void k_inv() {
    int i = blockIdx.x * blockDim.x + threadIdx.x;
    if (i < NN) d_inv[i] = 1.0f / fmaxf(d_cnt[i], 1.0f);
}
__global__ void k_zero_agg() {
    int i = blockIdx.x * blockDim.x + threadIdx.x;
    if (i < NN * HH / 4) ((float4*)d_agg)[i] = make_float4(0.f, 0.f, 0.f, 0.f);
}
__global__ __launch_bounds__(128) void k_gtab(const float* __restrict__ pe,
                                              const float* __restrict__ Wg,
                                              const float* __restrict__ bg) {
    __shared__ float ps[PDIM];
    int p = blockIdx.x;
    if (threadIdx.x < PDIM) ps[threadIdx.x] = pe[p * PDIM + threadIdx.x];
    __syncthreads();
    int j = threadIdx.x;
    float a = 0.0f;
    #pragma unroll 8
    for (int k = 0; k < PDIM; k++) a += ps[k] * Wg[k * HH + j];
    d_gtab[p * HH + j] = 2.0f * sigf(a + bg[j]);
}
// edge W^T images
__global__ void k_wimg(const float* __restrict__ Wt) {
    int t = blockIdx.x;
    unsigned char* wh = d_wimg + t * WIMGSZ;
    unsigned char* wl = wh + 34816;
    for (int i = threadIdx.x; i < 128 * 64; i += blockDim.x) {
        int n = i >> 6, k = (i & 63) * 2;
        float v0 = Wt[t * HH * HH + k * HH + n];
        float v1 = Wt[t * HH * HH + (k + 1) * HH + n];
        unsigned hi, lo;
        split2(v0, v1, hi, lo);
        int o = n * APITCH + k * 2;
        *(unsigned*)(wh + o) = hi;
        *(unsigned*)(wl + o) = lo;
    }
}
// GRU weight images: W is [384,128] row-major, already B[n=j][k]; pitched split
__global__ void k_wgru(const float* __restrict__ Wih, const float* __restrict__ Whh) {
    int m = blockIdx.y;
    const float* W = m ? Whh : Wih;
    unsigned char* wh = d_gruimg + m * 2 * IMGSEC;
    unsigned char* wl = wh + IMGSEC;
    for (int i = blockIdx.x * blockDim.x + threadIdx.x; i < 384 * 64; i += gridDim.x * blockDim.x) {
        int j = i >> 6, k = (i & 63) * 2;
        unsigned hi, lo;
        split2(W[j * 128 + k], W[j * 128 + k + 1], hi, lo);
        int o = j * APITCH + k * 2;
        *(unsigned*)(wh + o) = hi;
        *(unsigned*)(wl + o) = lo;
    }
}

// ---------------- edge phase: persistent HMMA bf16x3, B cached across tiles ----------------
__global__ __launch_bounds__(256) void k_edge(const float* __restrict__ bt, int flip) {
    extern __shared__ char smc[];
    int tid = threadIdx.x, wid = tid >> 5, lane = tid & 31;
    const float* __restrict__ h = flip ? d_hB : d_hA;
    int b1v = d_base[1], b2v = d_base[2];
    int ntiles = d_base[NT] >> 7;
    int tpb = (ntiles + 147) / 148;
    int t0 = blockIdx.x * tpb;
    int t1 = t0 + tpb;
    if (t1 > ntiles) t1 = ntiles;
    int cur = -1;

    int g = lane >> 2, tg = lane & 3;
    int rb = (wid >> 1) * 32, cb = (wid & 1) * 64;
    float* Cb = (float*)(smc + OF_C);

    for (int tile = t0; tile < t1; tile++) {
        int start = tile << 7;
        int t = (start >= b1v) + (start >= b2v);
        if (t != cur) {
            cur = t;
            const uint4* sp = (const uint4*)(d_wimg + t * WIMGSZ);
            uint4* dp = (uint4*)(smc + OF_BHI);
            for (int i = tid; i < WIMGSZ / 16; i += 256) dp[i] = sp[i];
            if (tid < 128) *(float*)(smc + OF_BIAS + 4 * tid) = bt[t * HH + tid];
        }
        // stage A: half row per thread (all 256 threads)
        {
            int r = tid >> 1, kb = (tid & 1) * 64;
            int s = d_es[start + r], pp = d_ps[start + r];
            const float4* hv = (const float4*)&h[s * HH + kb];
            const float4* gv = (const float4*)&d_gtab[pp * HH + kb];
            char* arh = smc + OF_AHI + r * APITCH + kb * 2;
            char* arl = smc + OF_ALO + r * APITCH + kb * 2;
            #pragma unroll 4
            for (int i = 0; i < 16; i++) {
                float4 a = hv[i], gg = gv[i];
                unsigned h0, l0, h1, l1;
                split2(a.x * gg.x, a.y * gg.y, h0, l0);
                split2(a.z * gg.z, a.w * gg.w, h1, l1);
                *(uint2*)(arh + i * 8) = make_uint2(h0, h1);
                *(uint2*)(arl + i * 8) = make_uint2(l0, l1);
            }
        }
        __syncthreads();

        float c[2][8][4];
        #pragma unroll
        for (int mt = 0; mt < 2; mt++)
            #pragma unroll
            for (int nt = 0; nt < 8; nt++)
                #pragma unroll
                for (int q = 0; q < 4; q++) c[mt][nt][q] = 0.0f;

        #pragma unroll
        for (int p = 0; p < 3; p++) {
            const char* Ab = smc + ((p < 2) ? OF_AHI : OF_ALO);
            const char* Bb = smc + ((p == 1) ? OF_BLO : OF_BHI);
            #pragma unroll
            for (int ks = 0; ks < 8; ks++) {
                int koff = (ks * 16 + tg * 2) * 2;
                unsigned a[2][4], b[8][2];
                #pragma unroll
                for (int mt = 0; mt < 2; mt++) {
                    const char* ar = Ab + (rb + mt * 16 + g) * APITCH + koff;
                    a[mt][0] = *(const unsigned*)(ar);
                    a[mt][1] = *(const unsigned*)(ar + 8 * APITCH);
                    a[mt][2] = *(const unsigned*)(ar + 16);
                    a[mt][3] = *(const unsigned*)(ar + 8 * APITCH + 16);
                }
                #pragma unroll
                for (int nt = 0; nt < 8; nt++) {
                    const char* br = Bb + (cb + nt * 8 + g) * APITCH + koff;
                    b[nt][0] = *(const unsigned*)(br);
                    b[nt][1] = *(const unsigned*)(br + 16);
                }
                #pragma unroll
                for (int mt = 0; mt < 2; mt++)
                    #pragma unroll
                    for (int nt = 0; nt < 8; nt++)
                        mma_bf16(c[mt][nt], a[mt], b[nt]);
            }
        }

        #pragma unroll
        for (int mt = 0; mt < 2; mt++)
            #pragma unroll
            for (int nt = 0; nt < 8; nt++) {
                int row = rb + mt * 16 + g, col = cb + nt * 8 + tg * 2;
                *(float2*)&Cb[row * CPITCH + col]       = make_float2(c[mt][nt][0], c[mt][nt][1]);
                *(float2*)&Cb[(row + 8) * CPITCH + col] = make_float2(c[mt][nt][2], c[mt][nt][3]);
            }
        __syncthreads();

        {
            int r = tid >> 1, c0 = (tid & 1) * 64;
            int d = d_ed[start + r];
            if (d >= 0) {
                float invd = d_inv[d];
                #pragma unroll 4
                for (int j = 0; j < 16; j++) {
                    float4 v  = *(float4*)&Cb[r * CPITCH + c0 + 4 * j];
                    float4 bb = *(float4*)(smc + OF_BIAS + 4 * (c0 + 4 * j));
                    red4(&d_agg[d * HH + c0 + 4 * j],
                         (v.x + bb.x) * invd, (v.y + bb.y) * invd,
                         (v.z + bb.z) * invd, (v.w + bb.w) * invd);
                }
            }
        }
        // next tile's B/A writes are ordered after this tile's reads by sync#1 + program order
    }
}

// ---------------- GRU GEMM: C[128,384-half] = A[128,128] @ W^T, HMMA bf16x3 ----------------
__global__ __launch_bounds__(256) void k_gemm384(const float* __restrict__ bias,
                                                 int which, int flip) {
    extern __shared__ char smc[];
    int tid = threadIdx.x, wid = tid >> 5, lane = tid & 31;
    int n0 = blockIdx.x * 128;
    int half = blockIdx.y;
    const float* __restrict__ A = which ? (flip ? d_hB : d_hA) : d_agg;
    float* __restrict__ Out = which ? d_gh : d_gi;
    const unsigned char* img = d_gruimg + which * 2 * IMGSEC;

    if (tid < GHALF) *(float*)(smc + OFG_BIAS + 4 * tid) = bias[half * GHALF + tid];

    if (tid < 128) {
        int r = tid, n = n0 + r;
        char* arh = smc + OFG_AHI + r * APITCH;
        char* arl = smc + OFG_ALO + r * APITCH;
        if (n < NN) {
            const float4* av = (const float4*)&A[n * HH];
            #pragma unroll 8
            for (int i = 0; i < 32; i++) {
                float4 a = av[i];
                unsigned h0, l0, h1, l1;
                split2(a.x, a.y, h0, l0);
                split2(a.z, a.w, h1, l1);
                *(uint2*)(arh + i * 8) = make_uint2(h0, h1);
                *(uint2*)(arl + i * 8) = make_uint2(l0, l1);
            }
        } else {
            #pragma unroll 8
            for (int i = 0; i < 32; i++) {
                *(uint2*)(arh + i * 8) = make_uint2(0u, 0u);
                *(uint2*)(arl + i * 8) = make_uint2(0u, 0u);
            }
        }
    } else {
        int idx = tid - 128;
        const uint4* sph = (const uint4*)(img + half * GHALF * APITCH);
        const uint4* spl = (const uint4*)(img + IMGSEC + half * GHALF * APITCH);
        uint4* dph = (uint4*)(smc + OFG_BHI);
        uint4* dpl = (uint4*)(smc + OFG_BLO);
        for (int i = idx; i < GHALF * APITCH / 16; i += 128) { dph[i] = sph[i]; dpl[i] = spl[i]; }
    }
    __syncthreads();

    int g = lane >> 2, tg = lane & 3;
    int rb = (wid & 3) * 32, cb = (wid >> 2) * 96;
    float c[2][12][4];
    #pragma unroll
    for (int mt = 0; mt < 2; mt++)
        #pragma unroll
        for (int nt = 0; nt < 12; nt++)
            #pragma unroll
            for (int q = 0; q < 4; q++) c[mt][nt][q] = 0.0f;

    #pragma unroll
    for (int p = 0; p < 3; p++) {
        const char* Ab = smc + ((p < 2) ? OFG_AHI : OFG_ALO);
        const char* Bb = smc + ((p == 1) ? OFG_BLO : OFG_BHI);
        #pragma unroll
        for (int ks = 0; ks < 8; ks++) {
            int koff = (ks * 16 + tg * 2) * 2;
            unsigned a[2][4], b[12][2];
            #pragma unroll
            for (int mt = 0; mt < 2; mt++) {
                const char* ar = Ab + (rb + mt * 16 + g) * APITCH + koff;
                a[mt][0] = *(const unsigned*)(ar);
                a[mt][1] = *(const unsigned*)(ar + 8 * APITCH);
                a[mt][2] = *(const unsigned*)(ar + 16);
                a[mt][3] = *(const unsigned*)(ar + 8 * APITCH + 16);
            }
            #pragma unroll
            for (int nt = 0; nt < 12; nt++) {
                const char* br = Bb + (cb + nt * 8 + g) * APITCH + koff;
                b[nt][0] = *(const unsigned*)(br);
                b[nt][1] = *(const unsigned*)(br + 16);
            }
            #pragma unroll
            for (int mt = 0; mt < 2; mt++)
                #pragma unroll
                for (int nt = 0; nt < 12; nt++)
                    mma_bf16(c[mt][nt], a[mt], b[nt]);
        }
    }

    #pragma unroll
    for (int mt = 0; mt < 2; mt++) {
        int row = rb + mt * 16 + g;
        int n1 = n0 + row, n2 = n1 + 8;
        #pragma unroll
        for (int nt = 0; nt < 12; nt++) {
            int col = cb + nt * 8 + tg * 2;
            float2 bb = *(float2*)(smc + OFG_BIAS + 4 * col);
            int gcol = half * GHALF + col;
            if (n1 < NN)
                *(float2*)&Out[n1 * 384 + gcol] = make_float2(c[mt][nt][0] + bb.x, c[mt][nt][1] + bb.y);
            if (n2 < NN)
                *(float2*)&Out[n2 * 384 + gcol] = make_float2(c[mt][nt][2] + bb.x, c[mt][nt][3] + bb.y);
        }
    }
}

// ---------------- GRU elementwise combine ----------------
__global__ void k_comb(int flip) {
    const float* __restrict__ h = flip ? d_hB : d_hA;
    float* __restrict__ hn      = flip ? d_hA : d_hB;
    int t = blockIdx.x * blockDim.x + threadIdx.x;
    if (t >= NN * 32) return;
    int n = t >> 5, q = (t & 31) * 4;
    const float* gp = &d_gi[n * 384];
    const float* mp = &d_gh[n * 384];
    float4 g0 = *(const float4*)&gp[q];
    float4 g1 = *(const float4*)&gp[128 + q];
    float4 g2 = *(const float4*)&gp[256 + q];
    float4 m0 = *(const float4*)&mp[q];
    float4 m1 = *(const float4*)&mp[128 + q];
    float4 m2 = *(const float4*)&mp[256 + q];
    float4 hh = *(const float4*)&h[n * HH + q];
    float4 o;
    { float r = sigf(g0.x + m0.x); float z = sigf(g1.x + m1.x);
      float nv = tanhf(g2.x + r * m2.x); o.x = (1.0f - z) * nv + z * hh.x; }
    { float r = sigf(g0.y + m0.y); float z = sigf(g1.y + m1.y);
      float nv = tanhf(g2.y + r * m2.y); o.y = (1.0f - z) * nv + z * hh.y; }
    { float r = sigf(g0.z + m0.z); float z = sigf(g1.z + m1.z);
      float nv = tanhf(g2.z + r * m2.z); o.z = (1.0f - z) * nv + z * hh.z; }
    { float r = sigf(g0.w + m0.w); float z = sigf(g1.w + m1.w);
      float nv = tanhf(g2.w + r * m2.w); o.w = (1.0f - z) * nv + z * hh.w; }
    *(float4*)&hn[n * HH + q] = o;
}

// ---------------- output ----------------
__global__ __launch_bounds__(256) void k_out(const float* __restrict__ W1,
                                             const float* __restrict__ b1,
                                             const float* __restrict__ W2,
                                             const float* __restrict__ b2,
                                             float* __restrict__ out) {
    extern __shared__ float sm[];
    float* Ws = sm;
    float* Xs = sm + 2 * HH * HH;
    for (int i = threadIdx.x; i < 2 * HH * HH / 4; i += 256)
        ((float4*)Ws)[i] = ((const float4*)W1)[i];
    int lane = threadIdx.x & 31, w = threadIdx.x >> 5;
    float4 bb = *(const float4*)&b1[4 * lane];
    float4 w2v = *(const float4*)&W2[4 * lane];
    float b2v = b2[0];
    __syncthreads();
    float* X = Xs + w * (ONT * 2 * 2 * HH);
    int gw = blockIdx.x * ONW + w;
    for (int n0 = gw * ONT; n0 < NN; n0 += 148 * ONW * ONT) {
        #pragma unroll
        for (int i = 0; i < ONT; i++) {
            float4 a = *(const float4*)&d_hA[(n0 + i) * HH + 4 * lane];
            float4 c = *(const float4*)&d_h0[(n0 + i) * HH + 4 * lane];
            float* xr = X + i * 512;
            *(float4*)(xr + 8 * lane)           = make_float4(a.x, a.x, a.y, a.y);
            *(float4*)(xr + 8 * lane + 4)       = make_float4(a.z, a.z, a.w, a.w);
            *(float4*)(xr + 256 + 8 * lane)     = make_float4(c.x, c.x, c.y, c.y);
            *(float4*)(xr + 256 + 8 * lane + 4) = make_float4(c.z, c.z, c.w, c.w);
        }
        __syncwarp();
        unsigned long long acc[ONT][2];
        #pragma unroll
        for (int i = 0; i < ONT; i++) { acc[i][0] = 0ull; acc[i][1] = 0ull; }
        #pragma unroll 4
        for (int k = 0; k < 2 * HH; k++) {
            ulonglong2 wv = *(const ulonglong2*)&Ws[k * HH + 4 * lane];
            #pragma unroll
            for (int i = 0; i < ONT; i++) {
                unsigned long long xk = *(const unsigned long long*)&X[i * 512 + 2 * k];
                fma2(acc[i][0], xk, wv.x);
                fma2(acc[i][1], xk, wv.y);
            }
        }
        #pragma unroll
        for (int i = 0; i < ONT; i++) {
            float2 p0 = up2(acc[i][0]), p1 = up2(acc[i][1]);
            float r0 = fmaxf(p0.x + bb.x, 0.f), r1 = fmaxf(p0.y + bb.y, 0.f);
            float r2 = fmaxf(p1.x + bb.z, 0.f), r3 = fmaxf(p1.y + bb.w, 0.f);
            float p = r0 * w2v.x + r1 * w2v.y + r2 * w2v.z + r3 * w2v.w;
            #pragma unroll
            for (int o = 16; o > 0; o >>= 1) p += __shfl_xor_sync(0xFFFFFFFFu, p, o);
            if (lane == 0) out[n0 + i] = p + b2v;
        }
        __syncwarp();
    }
}

// ---------------- launch ----------------
extern "C" void kernel_launch(void* const* d_in, const int* in_sizes, int n_in,
                              void* d_out, int out_size) {
    (void)in_sizes; (void)n_in; (void)out_size;
    const int*   xidx = (const int*)  d_in[0];
    const float* sel  = (const float*)d_in[1];
    const int*   eidx = (const int*)  d_in[2];
    const int*   et   = (const int*)  d_in[3];
    const int*   epos = (const int*)  d_in[4];
    const float* emb  = (const float*)d_in[5];
    const float* pe   = (const float*)d_in[6];
    const float* Wg   = (const float*)d_in[7];
    const float* bg   = (const float*)d_in[8];
    const float* Wt   = (const float*)d_in[9];
    const float* bt   = (const float*)d_in[10];
    const float* Wih  = (const float*)d_in[11];
    const float* Whh  = (const float*)d_in[12];
    const float* bih  = (const float*)d_in[13];
    const float* bhh  = (const float*)d_in[14];
    const float* W1   = (const float*)d_in[15];
    const float* b1   = (const float*)d_in[16];
    const float* W2   = (const float*)d_in[17];
    const float* b2   = (const float*)d_in[18];
    float* out = (float*)d_out;
    const int* src = eidx;
    const int* dst = eidx + EE;

    const int SM_OUT = (2 * HH * HH + ONW * ONT * 2 * 2 * HH) * 4;

    cudaFuncSetAttribute(k_edge,    cudaFuncAttributeMaxDynamicSharedMemorySize, SM_EDGE_BYTES);
    cudaFuncSetAttribute(k_gemm384, cudaFuncAttributeMaxDynamicSharedMemorySize, SM_G384);
    cudaFuncSetAttribute(k_out,     cudaFuncAttributeMaxDynamicSharedMemorySize, SM_OUT);

    k_init_pad<<<(PADE + 255) / 256, 256>>>();
    k_hist<<<(EE + 255) / 256, 256>>>(et);
    k_off<<<1, 1>>>();
    k_perm<<<(EE + 255) / 256, 256>>>(src, dst, et, epos);
    k_zero_cnt<<<(NN + 255) / 256, 256>>>();
    k_h0<<<(NN * 32 + 255) / 256, 256>>>(xidx, sel, emb);
    k_deg<<<(EE + 255) / 256, 256>>>(dst);
    k_inv<<<(NN + 255) / 256, 256>>>();
    k_gtab<<<NPOS, 128>>>(pe, Wg, bg);
    k_wimg<<<NT, 256>>>(Wt);
    k_wgru<<<dim3(96, 2), 256>>>(Wih, Whh);

    dim3 ggrid(NBX, 2);
    for (int it = 0; it < GITERS; it++) {
        int flip = it & 1;
        k_zero_agg<<<(NN * HH / 4 + 255) / 256, 256>>>();
        k_edge<<<148, 256, SM_EDGE_BYTES>>>(bt, flip);
        k_gemm384<<<ggrid, 256, SM_G384>>>(bih, 0, flip);
        k_gemm384<<<ggrid, 256, SM_G384>>>(bhh, 1, flip);
        k_comb<<<(NN * 32 + 255) / 256, 256>>>(flip);
    }
    k_out<<<148, 256, SM_OUT>>>(W1, b1, W2, b2, out);
}